// round 2
// baseline (speedup 1.0000x reference)
#include <cuda_runtime.h>
#include <math.h>

#define H_   16
#define DH_  64
#define B_   4
#define N_   2048
#define D_   1024
#define MTOT (B_*N_)     // 8192

// Scratch (static __device__ — no allocations allowed)
__device__ float g_Q[(size_t)B_*H_*N_*DH_];   // [b,h,n,d]
__device__ float g_K[(size_t)B_*H_*N_*DH_];
__device__ float g_V[(size_t)B_*H_*N_*DH_];
__device__ float g_A[(size_t)MTOT*D_];        // attention out, [b*n, h*d]

// ---------------------------------------------------------------------------
// SGEMM: C[M,N] = A[M,K] @ B[K,N]; 128x128 tile, K-step 8, 256 thr, 8x8 micro
// MODE 0: C = acc + bias[col]   (row-major store)
// MODE 1: scatter to g_Q  [b,h,n,d]
// MODE 2: scatter cols<1024 -> g_K, cols>=1024 -> g_V
// ---------------------------------------------------------------------------
template<int MODE>
__global__ __launch_bounds__(256)
void sgemm_kernel(const float* __restrict__ A, const float* __restrict__ B,
                  float* __restrict__ C, int M, int N, int K,
                  const float* __restrict__ bias)
{
    __shared__ float As[8][128];
    __shared__ float Bs[8][128];
    const int tid = threadIdx.x;
    const int tx = tid & 15, ty = tid >> 4;
    const int m0 = blockIdx.y * 128, n0 = blockIdx.x * 128;

    float acc[8][8];
#pragma unroll
    for (int i = 0; i < 8; i++)
#pragma unroll
        for (int j = 0; j < 8; j++) acc[i][j] = 0.f;

    const int arow = tid >> 1, akp = (tid & 1) * 4;
    const int bkr  = tid >> 5, bnc = (tid & 31) * 4;
    const float* Ap = A + (size_t)(m0 + arow) * K + akp;
    const float* Bp = B + (size_t)bkr * N + n0 + bnc;

    for (int k0 = 0; k0 < K; k0 += 8) {
        float4 av = *(const float4*)(Ap + k0);
        float4 bv = *(const float4*)(Bp + (size_t)k0 * N);
        As[akp+0][arow] = av.x;
        As[akp+1][arow] = av.y;
        As[akp+2][arow] = av.z;
        As[akp+3][arow] = av.w;
        *(float4*)&Bs[bkr][bnc] = bv;
        __syncthreads();
#pragma unroll
        for (int kk = 0; kk < 8; kk++) {
            float a[8], b[8];
            *(float4*)&a[0] = *(const float4*)&As[kk][ty*8];
            *(float4*)&a[4] = *(const float4*)&As[kk][ty*8+4];
            *(float4*)&b[0] = *(const float4*)&Bs[kk][tx*8];
            *(float4*)&b[4] = *(const float4*)&Bs[kk][tx*8+4];
#pragma unroll
            for (int i = 0; i < 8; i++)
#pragma unroll
                for (int j = 0; j < 8; j++)
                    acc[i][j] += a[i]*b[j];
        }
        __syncthreads();
    }

#pragma unroll
    for (int i = 0; i < 8; i++) {
        const int row  = m0 + ty*8 + i;
        const int col0 = n0 + tx*8;
        if (MODE == 0) {
            float r[8];
#pragma unroll
            for (int j = 0; j < 8; j++) r[j] = acc[i][j] + bias[col0+j];
            *(float4*)&C[(size_t)row*N + col0]     = *(float4*)&r[0];
            *(float4*)&C[(size_t)row*N + col0 + 4] = *(float4*)&r[4];
        } else {
            const int b = row >> 11;          // row / 2048
            const int n = row & 2047;
            if (MODE == 1) {
                const int h = col0 >> 6, d0 = col0 & 63;
                float* dst = g_Q + ((size_t)(b*H_ + h)*N_ + n)*DH_ + d0;
                *(float4*)&dst[0] = *(float4*)&acc[i][0];
                *(float4*)&dst[4] = *(float4*)&acc[i][4];
            } else {
                float* base = (col0 < 1024) ? g_K : g_V;
                const int c2 = (col0 < 1024) ? col0 : (col0 - 1024);
                const int h = c2 >> 6, d0 = c2 & 63;
                float* dst = base + ((size_t)(b*H_ + h)*N_ + n)*DH_ + d0;
                *(float4*)&dst[0] = *(float4*)&acc[i][0];
                *(float4*)&dst[4] = *(float4*)&acc[i][4];
            }
        }
    }
}

// ---------------------------------------------------------------------------
// RoPE on g_Q and g_K in place. Each thread handles a (d, d+32) pair.
// new[d]    = t1*cos(p[d])    - t2*sin(p[d])
// new[d+32] = t2*cos(p[d+32]) + t1*sin(p[d+32])
// ---------------------------------------------------------------------------
__global__ void rope_kernel(const float* __restrict__ rot)
{
    const int idx = blockIdx.x * blockDim.x + threadIdx.x;
    const int half = B_*H_*N_*32;
    if (idx >= 2*half) return;
    float* buf = g_Q;
    int t = idx;
    if (t >= half) { buf = g_K; t -= half; }
    const int d    = t & 31;
    const int rest = t >> 5;          // (b*H+h)*N + n
    const int n    = rest & (N_-1);
    const size_t i1 = (size_t)rest * 64 + d;
    const size_t i2 = i1 + 32;
    const float p1 = rot[n*64 + d];
    const float p2 = rot[n*64 + d + 32];
    const float t1 = buf[i1], t2 = buf[i2];
    buf[i1] = t1*cosf(p1) - t2*sinf(p1);
    buf[i2] = t2*cosf(p2) + t1*sinf(p2);
}

// ---------------------------------------------------------------------------
// Flash attention: grid (N/64, B*H), 256 threads, 64x64 tiles, online softmax.
// Per-thread 4x4 microtiles of S and O. Output -> g_A in [b*n, h*64+d].
// ---------------------------------------------------------------------------
#define ATTN_SMEM_FLOATS (3*4096 + 64*68)
#define ATTN_SMEM_BYTES  (ATTN_SMEM_FLOATS*4)

__global__ __launch_bounds__(256)
void attn_kernel()
{
    extern __shared__ float sm[];
    float* Qs = sm;            // [d][r]   4096
    float* Ks = sm + 4096;     // [d][c]   4096
    float* Vs = sm + 8192;     // [j][dc]  4096
    float* Ps = sm + 12288;    // [c][r] stride 68

    const int tid = threadIdx.x;
    const int tx = tid & 15, ty = tid >> 4;
    const int bh = blockIdx.y;
    const int m0 = blockIdx.x * 64;

    // Load Q tile, transposed to [d][row]
    const float* Qg = g_Q + ((size_t)bh * N_ + m0) * DH_;
    for (int t = tid; t < 1024; t += 256) {
        const int row = t >> 4, dp = (t & 15) * 4;
        float4 q = *(const float4*)(Qg + row*64 + dp);
        Qs[(dp+0)*64 + row] = q.x;
        Qs[(dp+1)*64 + row] = q.y;
        Qs[(dp+2)*64 + row] = q.z;
        Qs[(dp+3)*64 + row] = q.w;
    }

    float mi[4], li[4], o[4][4];
#pragma unroll
    for (int i = 0; i < 4; i++) {
        mi[i] = -1e30f; li[i] = 0.f;
#pragma unroll
        for (int j = 0; j < 4; j++) o[i][j] = 0.f;
    }

    for (int jt = 0; jt < N_/64; jt++) {
        const float* Kg = g_K + ((size_t)bh*N_ + jt*64)*DH_;
        const float* Vg = g_V + ((size_t)bh*N_ + jt*64)*DH_;
        __syncthreads();   // prior iter done with Ks/Vs/Ps (also covers Q load ordering)
        for (int t = tid; t < 1024; t += 256) {
            const int row = t >> 4, dp = (t & 15) * 4;
            float4 k = *(const float4*)(Kg + row*64 + dp);
            Ks[(dp+0)*64 + row] = k.x;
            Ks[(dp+1)*64 + row] = k.y;
            Ks[(dp+2)*64 + row] = k.z;
            Ks[(dp+3)*64 + row] = k.w;
            *(float4*)&Vs[row*64 + dp] = *(const float4*)(Vg + row*64 + dp);
        }
        __syncthreads();

        // S = Q K^T (4x4 per thread)
        float s[4][4];
#pragma unroll
        for (int i = 0; i < 4; i++)
#pragma unroll
            for (int j = 0; j < 4; j++) s[i][j] = 0.f;
#pragma unroll 8
        for (int d = 0; d < 64; d++) {
            float qa[4], kb[4];
            *(float4*)qa = *(const float4*)&Qs[d*64 + ty*4];
            *(float4*)kb = *(const float4*)&Ks[d*64 + tx*4];
#pragma unroll
            for (int i = 0; i < 4; i++)
#pragma unroll
                for (int j = 0; j < 4; j++)
                    s[i][j] += qa[i]*kb[j];
        }

        // online softmax (rows distributed across 16-lane tx groups)
#pragma unroll
        for (int i = 0; i < 4; i++) {
            float mx = -1e30f;
#pragma unroll
            for (int j = 0; j < 4; j++) { s[i][j] *= 0.125f; mx = fmaxf(mx, s[i][j]); }
#pragma unroll
            for (int off = 8; off >= 1; off >>= 1)
                mx = fmaxf(mx, __shfl_xor_sync(0xffffffffu, mx, off));
            const float mnew  = fmaxf(mi[i], mx);
            const float alpha = __expf(mi[i] - mnew);
            float rs = 0.f;
#pragma unroll
            for (int j = 0; j < 4; j++) { const float p = __expf(s[i][j]-mnew); s[i][j] = p; rs += p; }
#pragma unroll
            for (int off = 8; off >= 1; off >>= 1)
                rs += __shfl_xor_sync(0xffffffffu, rs, off);
            li[i] = li[i]*alpha + rs;
            mi[i] = mnew;
#pragma unroll
            for (int j = 0; j < 4; j++) o[i][j] *= alpha;
#pragma unroll
            for (int j = 0; j < 4; j++) Ps[(tx*4+j)*68 + ty*4 + i] = s[i][j];
        }
        __syncthreads();

        // O += P @ V
#pragma unroll 8
        for (int j = 0; j < 64; j++) {
            float pr[4], vd[4];
            *(float4*)pr = *(const float4*)&Ps[j*68 + ty*4];
            *(float4*)vd = *(const float4*)&Vs[j*64 + tx*4];
#pragma unroll
            for (int i = 0; i < 4; i++)
#pragma unroll
                for (int jj = 0; jj < 4; jj++)
                    o[i][jj] += pr[i]*vd[jj];
        }
    }

    // epilogue: normalize and write to [b*n, h*64+d]
    const int b = bh >> 4, h = bh & 15;
#pragma unroll
    for (int i = 0; i < 4; i++) {
        const float inv = 1.f / li[i];
        const int row = m0 + ty*4 + i;
        float r[4];
#pragma unroll
        for (int j = 0; j < 4; j++) r[j] = o[i][j]*inv;
        float* dst = g_A + ((size_t)(b*N_ + row))*D_ + h*64 + tx*4;
        *(float4*)dst = *(float4*)r;
    }
}

// ---------------------------------------------------------------------------
extern "C" void kernel_launch(void* const* d_in, const int* in_sizes, int n_in,
                              void* d_out, int out_size)
{
    const float* x    = (const float*)d_in[0];
    const float* rot  = (const float*)d_in[1];
    const float* Wq   = (const float*)d_in[2];
    const float* Wkv  = (const float*)d_in[3];
    const float* Wout = (const float*)d_in[4];
    const float* bout = (const float*)d_in[5];
    float* out = (float*)d_out;

    float* gA = nullptr;
    cudaGetSymbolAddress((void**)&gA, g_A);
    cudaFuncSetAttribute(attn_kernel,
                         cudaFuncAttributeMaxDynamicSharedMemorySize,
                         ATTN_SMEM_BYTES);

    // Q = X @ Wq  -> g_Q [b,h,n,d]
    sgemm_kernel<1><<<dim3(8, 64), 256>>>(x, Wq, nullptr, MTOT, 1024, 1024, nullptr);
    // KV = X @ Wkv -> g_K / g_V
    sgemm_kernel<2><<<dim3(16, 64), 256>>>(x, Wkv, nullptr, MTOT, 2048, 1024, nullptr);
    // RoPE in place on g_Q, g_K
    rope_kernel<<<(2*B_*H_*N_*32 + 255)/256, 256>>>(rot);
    // attention -> g_A [b*n, h*d]
    attn_kernel<<<dim3(N_/64, B_*H_), 256, ATTN_SMEM_BYTES>>>();
    // out = g_A @ Wout + bout
    sgemm_kernel<0><<<dim3(8, 64), 256>>>(gA, Wout, out, MTOT, 1024, 1024, bout);
}

// round 3
// speedup vs baseline: 3.2963x; 3.2963x over previous
#include <cuda_runtime.h>
#include <math.h>

#define H_   16
#define DH_  64
#define B_   4
#define N_   2048
#define D_   1024
#define MTOT (B_*N_)     // 8192

__device__ float g_Q[(size_t)B_*H_*N_*DH_];   // [b,h,n,d]
__device__ float g_K[(size_t)B_*H_*N_*DH_];
__device__ float g_V[(size_t)B_*H_*N_*DH_];
__device__ float g_A[(size_t)MTOT*D_];        // attention out, [b*n, h*d]

// ---------------------------------------------------------------------------
// helpers
// ---------------------------------------------------------------------------
__device__ __forceinline__ unsigned f2tf(float f) {
    unsigned u; asm("cvt.rna.tf32.f32 %0, %1;" : "=r"(u) : "f"(f)); return u;
}
__device__ __forceinline__ float uaf(unsigned u) { return __uint_as_float(u); }
__device__ __forceinline__ unsigned fau(float f) { return __float_as_uint(f); }

__device__ __forceinline__ void mma8(float* c, const unsigned* a, const unsigned* b) {
    asm volatile("mma.sync.aligned.m16n8k8.row.col.f32.tf32.tf32.f32 "
                 "{%0,%1,%2,%3}, {%4,%5,%6,%7}, {%8,%9}, {%0,%1,%2,%3};"
                 : "+f"(c[0]), "+f"(c[1]), "+f"(c[2]), "+f"(c[3])
                 : "r"(a[0]), "r"(a[1]), "r"(a[2]), "r"(a[3]),
                   "r"(b[0]), "r"(b[1]));
}

// ---------------------------------------------------------------------------
// TF32 GEMM: C[M,N] = A @ B. 128x128 block, BK=16, 256 thr, warp tile 32x64.
// MODE 0: C = acc + bias  (row-major)
// MODE 1: scatter to g_Q  [b,h,n,d]
// MODE 2: cols<1024 -> g_K, cols>=1024 -> g_V
// ---------------------------------------------------------------------------
#define GSTRIDE 136
template<int MODE>
__global__ __launch_bounds__(256)
void gemm_tf32(const float* __restrict__ A, const float* __restrict__ Bm,
               float* __restrict__ C, int M, int N, int K,
               const float* __restrict__ bias)
{
    __shared__ float As[16][GSTRIDE];
    __shared__ float Bs[16][GSTRIDE];
    const int tid  = threadIdx.x;
    const int lane = tid & 31;
    const int wid  = tid >> 5;
    const int wm   = wid & 3;          // 4 warps in m -> 32 rows each
    const int wn   = wid >> 2;         // 2 warps in n -> 64 cols each
    const int m0 = blockIdx.y * 128, n0 = blockIdx.x * 128;

    float acc[2][8][4];
#pragma unroll
    for (int i = 0; i < 2; i++)
#pragma unroll
        for (int j = 0; j < 8; j++)
#pragma unroll
            for (int v = 0; v < 4; v++) acc[i][j][v] = 0.f;

    // global load mapping
    const int arow = tid >> 2, ac4 = (tid & 3) * 4;      // A: 2x float4 (rows arow, arow+64)
    const int bkr  = tid >> 5, bnc = (tid & 31) * 4;     // B: 2x float4 (k bkr, bkr+8)
    const float* Ap = A  + (size_t)(m0 + arow) * K + ac4;
    const float* Bp = Bm + (size_t)bkr * N + n0 + bnc;

    float4 a0 = *(const float4*)(Ap);
    float4 a1 = *(const float4*)(Ap + (size_t)64 * K);
    float4 b0 = *(const float4*)(Bp);
    float4 b1 = *(const float4*)(Bp + (size_t)8 * N);

    for (int k0 = 0; k0 < K; k0 += 16) {
        // store stage (convert to tf32 bits once here)
        As[ac4+0][arow] = uaf(f2tf(a0.x));
        As[ac4+1][arow] = uaf(f2tf(a0.y));
        As[ac4+2][arow] = uaf(f2tf(a0.z));
        As[ac4+3][arow] = uaf(f2tf(a0.w));
        As[ac4+0][arow+64] = uaf(f2tf(a1.x));
        As[ac4+1][arow+64] = uaf(f2tf(a1.y));
        As[ac4+2][arow+64] = uaf(f2tf(a1.z));
        As[ac4+3][arow+64] = uaf(f2tf(a1.w));
        Bs[bkr][bnc+0] = uaf(f2tf(b0.x));
        Bs[bkr][bnc+1] = uaf(f2tf(b0.y));
        Bs[bkr][bnc+2] = uaf(f2tf(b0.z));
        Bs[bkr][bnc+3] = uaf(f2tf(b0.w));
        Bs[bkr+8][bnc+0] = uaf(f2tf(b1.x));
        Bs[bkr+8][bnc+1] = uaf(f2tf(b1.y));
        Bs[bkr+8][bnc+2] = uaf(f2tf(b1.z));
        Bs[bkr+8][bnc+3] = uaf(f2tf(b1.w));
        __syncthreads();

        if (k0 + 16 < K) {   // prefetch next stage
            Ap += 16;  Bp += (size_t)16 * N;
            a0 = *(const float4*)(Ap);
            a1 = *(const float4*)(Ap + (size_t)64 * K);
            b0 = *(const float4*)(Bp);
            b1 = *(const float4*)(Bp + (size_t)8 * N);
        }

#pragma unroll
        for (int ks = 0; ks < 2; ks++) {
            const int kk = ks * 8 + (lane & 3);
            unsigned af[2][4], bf[8][2];
#pragma unroll
            for (int mt = 0; mt < 2; mt++) {
                const int r = wm*32 + mt*16 + (lane >> 2);
                af[mt][0] = fau(As[kk  ][r]);
                af[mt][1] = fau(As[kk  ][r+8]);
                af[mt][2] = fau(As[kk+4][r]);
                af[mt][3] = fau(As[kk+4][r+8]);
            }
#pragma unroll
            for (int nt = 0; nt < 8; nt++) {
                const int c = wn*64 + nt*8 + (lane >> 2);
                bf[nt][0] = fau(Bs[kk  ][c]);
                bf[nt][1] = fau(Bs[kk+4][c]);
            }
#pragma unroll
            for (int mt = 0; mt < 2; mt++)
#pragma unroll
                for (int nt = 0; nt < 8; nt++)
                    mma8(acc[mt][nt], af[mt], bf[nt]);
        }
        __syncthreads();
    }

    // epilogue
#pragma unroll
    for (int mt = 0; mt < 2; mt++) {
        const int r0 = m0 + wm*32 + mt*16 + (lane >> 2);
#pragma unroll
        for (int nt = 0; nt < 8; nt++) {
            const int c = n0 + wn*64 + nt*8 + (lane & 3)*2;
#pragma unroll
            for (int half = 0; half < 2; half++) {
                const int row = r0 + half*8;
                float2 v;
                v.x = acc[mt][nt][half*2+0];
                v.y = acc[mt][nt][half*2+1];
                if (MODE == 0) {
                    v.x += bias[c]; v.y += bias[c+1];
                    *(float2*)&C[(size_t)row*N + c] = v;
                } else {
                    const int b = row >> 11, n = row & 2047;
                    if (MODE == 1) {
                        const int h = c >> 6, d = c & 63;
                        *(float2*)&g_Q[((size_t)(b*H_+h)*N_ + n)*DH_ + d] = v;
                    } else {
                        float* base = (c < 1024) ? g_K : g_V;
                        const int c2 = c & 1023;
                        const int h = c2 >> 6, d = c2 & 63;
                        *(float2*)&base[((size_t)(b*H_+h)*N_ + n)*DH_ + d] = v;
                    }
                }
            }
        }
    }
}

// ---------------------------------------------------------------------------
// RoPE on g_Q and g_K in place (pair (d, d+32))
// ---------------------------------------------------------------------------
__global__ void rope_kernel(const float* __restrict__ rot)
{
    const int idx = blockIdx.x * blockDim.x + threadIdx.x;
    const int half = B_*H_*N_*32;
    if (idx >= 2*half) return;
    float* buf = g_Q;
    int t = idx;
    if (t >= half) { buf = g_K; t -= half; }
    const int d    = t & 31;
    const int rest = t >> 5;
    const int n    = rest & (N_-1);
    const size_t i1 = (size_t)rest * 64 + d;
    const size_t i2 = i1 + 32;
    const float p1 = rot[n*64 + d];
    const float p2 = rot[n*64 + d + 32];
    const float t1 = buf[i1], t2 = buf[i2];
    buf[i1] = t1*cosf(p1) - t2*sinf(p1);
    buf[i2] = t2*cosf(p2) + t1*sinf(p2);
}

// ---------------------------------------------------------------------------
// Flash attention with TF32 MMA.
// Grid (N/64, B*H); 128 threads = 4 warps; each warp owns 16 Q rows.
// Ks[j][d] stride 68, Vs[j][d] stride 72, Ps[r][j] stride 68.
// ---------------------------------------------------------------------------
#define KS_STRIDE 68
#define VS_STRIDE 72
#define PS_STRIDE 68
#define ATT_SMEM_FLOATS (64*KS_STRIDE + 64*VS_STRIDE + 64*PS_STRIDE)
#define ATT_SMEM_BYTES  (ATT_SMEM_FLOATS*4)

__global__ __launch_bounds__(128)
void attn_mma()
{
    extern __shared__ float sm[];
    float* Ks = sm;                        // [64][68]  (j, d)
    float* Vs = sm + 64*KS_STRIDE;         // [64][72]  (j, d)
    float* Ps = sm + 64*KS_STRIDE + 64*VS_STRIDE;  // [64][68] (r, j)

    const int tid  = threadIdx.x;
    const int lane = tid & 31;
    const int wid  = tid >> 5;
    const int bh = blockIdx.y;
    const int m0 = blockIdx.x * 64;

    // --- Q fragments cached in registers (scaled by 1/8, tf32) ---
    const float* Qb = g_Q + (size_t)bh * N_ * DH_;
    const int qr = m0 + wid*16 + (lane >> 2);
    unsigned qf[8][4];
#pragma unroll
    for (int ks = 0; ks < 8; ks++) {
        const int kk = ks*8 + (lane & 3);
        qf[ks][0] = f2tf(Qb[(size_t)qr*64      + kk  ] * 0.125f);
        qf[ks][1] = f2tf(Qb[(size_t)(qr+8)*64  + kk  ] * 0.125f);
        qf[ks][2] = f2tf(Qb[(size_t)qr*64      + kk+4] * 0.125f);
        qf[ks][3] = f2tf(Qb[(size_t)(qr+8)*64  + kk+4] * 0.125f);
    }

    float mi[2] = {-1e30f, -1e30f};
    float li[2] = {0.f, 0.f};
    float o[8][4];
#pragma unroll
    for (int nt = 0; nt < 8; nt++)
#pragma unroll
        for (int v = 0; v < 4; v++) o[nt][v] = 0.f;

    for (int jt = 0; jt < N_/64; jt++) {
        const float* Kg = g_K + ((size_t)bh*N_ + jt*64) * DH_;
        const float* Vg = g_V + ((size_t)bh*N_ + jt*64) * DH_;
        __syncthreads();                       // prev iter done with Ks/Vs
        for (int t = tid; t < 1024; t += 128) {
            const int row = t >> 4, c4 = (t & 15) * 4;
            float4 k4 = *(const float4*)(Kg + row*64 + c4);
            float* kd = &Ks[row*KS_STRIDE + c4];
            kd[0] = uaf(f2tf(k4.x)); kd[1] = uaf(f2tf(k4.y));
            kd[2] = uaf(f2tf(k4.z)); kd[3] = uaf(f2tf(k4.w));
            float4 v4 = *(const float4*)(Vg + row*64 + c4);
            float* vd = &Vs[row*VS_STRIDE + c4];
            vd[0] = uaf(f2tf(v4.x)); vd[1] = uaf(f2tf(v4.y));
            vd[2] = uaf(f2tf(v4.z)); vd[3] = uaf(f2tf(v4.w));
        }
        __syncthreads();

        // --- S = (Q/8) K^T ---
        float s[8][4];
#pragma unroll
        for (int nt = 0; nt < 8; nt++)
#pragma unroll
            for (int v = 0; v < 4; v++) s[nt][v] = 0.f;
#pragma unroll
        for (int ks = 0; ks < 8; ks++) {
            const int kk = ks*8 + (lane & 3);
            unsigned bf[8][2];
#pragma unroll
            for (int nt = 0; nt < 8; nt++) {
                const int n = nt*8 + (lane >> 2);
                bf[nt][0] = fau(Ks[n*KS_STRIDE + kk  ]);
                bf[nt][1] = fau(Ks[n*KS_STRIDE + kk+4]);
            }
#pragma unroll
            for (int nt = 0; nt < 8; nt++)
                mma8(s[nt], qf[ks], bf[nt]);
        }

        // --- online softmax (2 rows per lane: qrow, qrow+8) ---
        float mx0 = -1e30f, mx1 = -1e30f;
#pragma unroll
        for (int nt = 0; nt < 8; nt++) {
            mx0 = fmaxf(mx0, fmaxf(s[nt][0], s[nt][1]));
            mx1 = fmaxf(mx1, fmaxf(s[nt][2], s[nt][3]));
        }
#pragma unroll
        for (int off = 1; off <= 2; off <<= 1) {
            mx0 = fmaxf(mx0, __shfl_xor_sync(0xffffffffu, mx0, off));
            mx1 = fmaxf(mx1, __shfl_xor_sync(0xffffffffu, mx1, off));
        }
        const float mn0 = fmaxf(mi[0], mx0);
        const float mn1 = fmaxf(mi[1], mx1);
        const float al0 = __expf(mi[0] - mn0);
        const float al1 = __expf(mi[1] - mn1);
        float rs0 = 0.f, rs1 = 0.f;
#pragma unroll
        for (int nt = 0; nt < 8; nt++) {
            float p0 = __expf(s[nt][0] - mn0);
            float p1 = __expf(s[nt][1] - mn0);
            float p2 = __expf(s[nt][2] - mn1);
            float p3 = __expf(s[nt][3] - mn1);
            s[nt][0] = p0; s[nt][1] = p1; s[nt][2] = p2; s[nt][3] = p3;
            rs0 += p0 + p1; rs1 += p2 + p3;
        }
#pragma unroll
        for (int off = 1; off <= 2; off <<= 1) {
            rs0 += __shfl_xor_sync(0xffffffffu, rs0, off);
            rs1 += __shfl_xor_sync(0xffffffffu, rs1, off);
        }
        li[0] = li[0]*al0 + rs0;  mi[0] = mn0;
        li[1] = li[1]*al1 + rs1;  mi[1] = mn1;
#pragma unroll
        for (int nt = 0; nt < 8; nt++) {
            o[nt][0] *= al0; o[nt][1] *= al0;
            o[nt][2] *= al1; o[nt][3] *= al1;
        }

        // --- store P (tf32) into per-warp-private rows of Ps ---
        {
            const int r0 = wid*16 + (lane >> 2);
#pragma unroll
            for (int nt = 0; nt < 8; nt++) {
                const int c = nt*8 + (lane & 3)*2;
                float2 lo, hi;
                lo.x = uaf(f2tf(s[nt][0])); lo.y = uaf(f2tf(s[nt][1]));
                hi.x = uaf(f2tf(s[nt][2])); hi.y = uaf(f2tf(s[nt][3]));
                *(float2*)&Ps[r0*PS_STRIDE + c]     = lo;
                *(float2*)&Ps[(r0+8)*PS_STRIDE + c] = hi;
            }
        }
        __syncwarp();

        // --- O += P @ V ---
#pragma unroll
        for (int ks = 0; ks < 8; ks++) {
            const int kk = ks*8 + (lane & 3);
            const int r0 = wid*16 + (lane >> 2);
            unsigned af[4], bf[8][2];
            af[0] = fau(Ps[r0*PS_STRIDE     + kk  ]);
            af[1] = fau(Ps[(r0+8)*PS_STRIDE + kk  ]);
            af[2] = fau(Ps[r0*PS_STRIDE     + kk+4]);
            af[3] = fau(Ps[(r0+8)*PS_STRIDE + kk+4]);
#pragma unroll
            for (int nt = 0; nt < 8; nt++) {
                const int n = nt*8 + (lane >> 2);
                bf[nt][0] = fau(Vs[kk*VS_STRIDE     + n]);
                bf[nt][1] = fau(Vs[(kk+4)*VS_STRIDE + n]);
            }
#pragma unroll
            for (int nt = 0; nt < 8; nt++)
                mma8(o[nt], af, bf[nt]);
        }
        __syncwarp();
    }

    // --- epilogue: normalize + write [b*n, h*64+d] ---
    const int b = bh >> 4, h = bh & 15;
    const float inv0 = 1.f / li[0];
    const float inv1 = 1.f / li[1];
    const int r0 = m0 + wid*16 + (lane >> 2);
#pragma unroll
    for (int nt = 0; nt < 8; nt++) {
        const int c = h*64 + nt*8 + (lane & 3)*2;
        float2 lo, hi;
        lo.x = o[nt][0]*inv0; lo.y = o[nt][1]*inv0;
        hi.x = o[nt][2]*inv1; hi.y = o[nt][3]*inv1;
        *(float2*)&g_A[((size_t)(b*N_ + r0))*D_ + c]     = lo;
        *(float2*)&g_A[((size_t)(b*N_ + r0 + 8))*D_ + c] = hi;
    }
}

// ---------------------------------------------------------------------------
extern "C" void kernel_launch(void* const* d_in, const int* in_sizes, int n_in,
                              void* d_out, int out_size)
{
    const float* x    = (const float*)d_in[0];
    const float* rot  = (const float*)d_in[1];
    const float* Wq   = (const float*)d_in[2];
    const float* Wkv  = (const float*)d_in[3];
    const float* Wout = (const float*)d_in[4];
    const float* bout = (const float*)d_in[5];
    float* out = (float*)d_out;

    float* gA = nullptr;
    cudaGetSymbolAddress((void**)&gA, g_A);
    cudaFuncSetAttribute(attn_mma,
                         cudaFuncAttributeMaxDynamicSharedMemorySize,
                         ATT_SMEM_BYTES);

    gemm_tf32<1><<<dim3(8, 64),  256>>>(x,  Wq,  nullptr, MTOT, 1024, 1024, nullptr);
    gemm_tf32<2><<<dim3(16, 64), 256>>>(x,  Wkv, nullptr, MTOT, 2048, 1024, nullptr);
    rope_kernel<<<(2*B_*H_*N_*32 + 255)/256, 256>>>(rot);
    attn_mma<<<dim3(N_/64, B_*H_), 128, ATT_SMEM_BYTES>>>();
    gemm_tf32<0><<<dim3(8, 64),  256>>>(gA, Wout, out, MTOT, 1024, 1024, bout);
}

// round 4
// speedup vs baseline: 3.5580x; 1.0794x over previous
#include <cuda_runtime.h>
#include <math.h>

#define H_   16
#define DH_  64
#define B_   4
#define N_   2048
#define D_   1024
#define MTOT (B_*N_)     // 8192

__device__ float g_Q[(size_t)B_*H_*N_*DH_];   // [b,h,n,d]
__device__ float g_K[(size_t)B_*H_*N_*DH_];
__device__ float g_V[(size_t)B_*H_*N_*DH_];
__device__ float g_A[(size_t)MTOT*D_];        // attention out, [b*n, h*d]

// ---------------------------------------------------------------------------
// helpers
// ---------------------------------------------------------------------------
__device__ __forceinline__ unsigned f2tf(float f) {
    unsigned u; asm("cvt.rna.tf32.f32 %0, %1;" : "=r"(u) : "f"(f)); return u;
}
__device__ __forceinline__ float uaf(unsigned u) { return __uint_as_float(u); }
__device__ __forceinline__ unsigned fau(float f) { return __float_as_uint(f); }
__device__ __forceinline__ unsigned sptr(const void* p) {
    return (unsigned)__cvta_generic_to_shared(p);
}
__device__ __forceinline__ void mma8(float* c, const unsigned* a, const unsigned* b) {
    asm volatile("mma.sync.aligned.m16n8k8.row.col.f32.tf32.tf32.f32 "
                 "{%0,%1,%2,%3}, {%4,%5,%6,%7}, {%8,%9}, {%0,%1,%2,%3};"
                 : "+f"(c[0]), "+f"(c[1]), "+f"(c[2]), "+f"(c[3])
                 : "r"(a[0]), "r"(a[1]), "r"(a[2]), "r"(a[3]),
                   "r"(b[0]), "r"(b[1]));
}
__device__ __forceinline__ void ldsm4(unsigned& r0, unsigned& r1,
                                      unsigned& r2, unsigned& r3, unsigned addr) {
    asm volatile("ldmatrix.sync.aligned.m8n8.x4.shared.b16 {%0,%1,%2,%3}, [%4];"
                 : "=r"(r0), "=r"(r1), "=r"(r2), "=r"(r3) : "r"(addr));
}

// ---------------------------------------------------------------------------
// TF32 GEMM with ldmatrix. 128x128 block, BK=16, 256 thr, warp tile 32x64.
// As layout [m][k] stride 20, Bs layout [n][k] stride 20 (both ldmatrix-ready).
// MODE 0: C = acc + bias; MODE 1: scatter g_Q; MODE 2: K plain / V tf32-rounded
// ---------------------------------------------------------------------------
#define GST 20
template<int MODE>
__global__ __launch_bounds__(256)
void gemm_tf32(const float* __restrict__ A, const float* __restrict__ Bm,
               float* __restrict__ C, int M, int N, int K,
               const float* __restrict__ bias)
{
    __shared__ float As[128*GST];
    __shared__ float Bs[128*GST];
    const int tid  = threadIdx.x;
    const int lane = tid & 31;
    const int wid  = tid >> 5;
    const int wm   = wid & 3;
    const int wn   = wid >> 2;
    const int m0 = blockIdx.y * 128, n0 = blockIdx.x * 128;

    float acc[2][8][4];
#pragma unroll
    for (int i = 0; i < 2; i++)
#pragma unroll
        for (int j = 0; j < 8; j++)
#pragma unroll
            for (int v = 0; v < 4; v++) acc[i][j][v] = 0.f;

    // staging mapping
    const int am  = tid >> 1,  ako = (tid & 1) * 8;    // A: [m][k] direct
    const int bn  = tid & 127, bkh = (tid >> 7) * 8;   // B: transpose per-scalar LDG
    const float* Ap = A  + (size_t)(m0 + am) * K + ako;
    const float* Bp = Bm + n0 + bn;

    float4 a0 = *(const float4*)(Ap);
    float4 a1 = *(const float4*)(Ap + 4);
    float br[8];
#pragma unroll
    for (int i = 0; i < 8; i++) br[i] = Bp[(size_t)(bkh + i) * N];

    // fragment ldmatrix base addresses
    unsigned aAd[2], bAd[4];
#pragma unroll
    for (int mt = 0; mt < 2; mt++)
        aAd[mt] = sptr(&As[(wm*32 + mt*16 + ((lane>>3)&1)*8 + (lane&7))*GST
                           + (lane>>4)*4]);
#pragma unroll
    for (int p = 0; p < 4; p++)
        bAd[p] = sptr(&Bs[(wn*64 + p*16 + ((lane>>4)&1)*8 + (lane&7))*GST
                          + ((lane>>3)&1)*4]);

    for (int k0 = 0; k0 < K; k0 += 16) {
        // stage (convert to tf32 at store)
        float4 w;
        w.x = uaf(f2tf(a0.x)); w.y = uaf(f2tf(a0.y));
        w.z = uaf(f2tf(a0.z)); w.w = uaf(f2tf(a0.w));
        *(float4*)&As[am*GST + ako] = w;
        w.x = uaf(f2tf(a1.x)); w.y = uaf(f2tf(a1.y));
        w.z = uaf(f2tf(a1.z)); w.w = uaf(f2tf(a1.w));
        *(float4*)&As[am*GST + ako + 4] = w;
        w.x = uaf(f2tf(br[0])); w.y = uaf(f2tf(br[1]));
        w.z = uaf(f2tf(br[2])); w.w = uaf(f2tf(br[3]));
        *(float4*)&Bs[bn*GST + bkh] = w;
        w.x = uaf(f2tf(br[4])); w.y = uaf(f2tf(br[5]));
        w.z = uaf(f2tf(br[6])); w.w = uaf(f2tf(br[7]));
        *(float4*)&Bs[bn*GST + bkh + 4] = w;
        __syncthreads();

        if (k0 + 16 < K) {   // prefetch next stage
            Ap += 16;
            a0 = *(const float4*)(Ap);
            a1 = *(const float4*)(Ap + 4);
#pragma unroll
            for (int i = 0; i < 8; i++)
                br[i] = Bp[(size_t)(k0 + 16 + bkh + i) * N];
        }

#pragma unroll
        for (int ks = 0; ks < 2; ks++) {
            unsigned af[2][4];
            ldsm4(af[0][0], af[0][1], af[0][2], af[0][3], aAd[0] + ks*32);
            ldsm4(af[1][0], af[1][1], af[1][2], af[1][3], aAd[1] + ks*32);
#pragma unroll
            for (int p = 0; p < 4; p++) {
                unsigned bb[4];
                ldsm4(bb[0], bb[1], bb[2], bb[3], bAd[p] + ks*32);
#pragma unroll
                for (int mt = 0; mt < 2; mt++) {
                    mma8(acc[mt][2*p+0], af[mt], &bb[0]);
                    mma8(acc[mt][2*p+1], af[mt], &bb[2]);
                }
            }
        }
        __syncthreads();
    }

    // epilogue
#pragma unroll
    for (int mt = 0; mt < 2; mt++) {
        const int r0 = m0 + wm*32 + mt*16 + (lane >> 2);
#pragma unroll
        for (int nt = 0; nt < 8; nt++) {
            const int c = n0 + wn*64 + nt*8 + (lane & 3)*2;
#pragma unroll
            for (int half = 0; half < 2; half++) {
                const int row = r0 + half*8;
                float2 v;
                v.x = acc[mt][nt][half*2+0];
                v.y = acc[mt][nt][half*2+1];
                if (MODE == 0) {
                    v.x += bias[c]; v.y += bias[c+1];
                    *(float2*)&C[(size_t)row*N + c] = v;
                } else {
                    const int b = row >> 11, n = row & 2047;
                    if (MODE == 1) {
                        const int h = c >> 6, d = c & 63;
                        *(float2*)&g_Q[((size_t)(b*H_+h)*N_ + n)*DH_ + d] = v;
                    } else {
                        const bool isV = (c >= 1024);
                        if (isV) {   // pre-round V to tf32 (attention copies raw)
                            v.x = uaf(f2tf(v.x));
                            v.y = uaf(f2tf(v.y));
                        }
                        float* base = isV ? g_V : g_K;
                        const int c2 = c & 1023;
                        const int h = c2 >> 6, d = c2 & 63;
                        *(float2*)&base[((size_t)(b*H_+h)*N_ + n)*DH_ + d] = v;
                    }
                }
            }
        }
    }
}

// ---------------------------------------------------------------------------
// RoPE on g_Q and g_K in place (pair (d, d+32)); stores tf32-rounded values.
// ---------------------------------------------------------------------------
__global__ void rope_kernel(const float* __restrict__ rot)
{
    const int idx = blockIdx.x * blockDim.x + threadIdx.x;
    const int half = B_*H_*N_*32;
    if (idx >= 2*half) return;
    float* buf = g_Q;
    int t = idx;
    if (t >= half) { buf = g_K; t -= half; }
    const int d    = t & 31;
    const int rest = t >> 5;
    const int n    = rest & (N_-1);
    const size_t i1 = (size_t)rest * 64 + d;
    const size_t i2 = i1 + 32;
    const float p1 = rot[n*64 + d];
    const float p2 = rot[n*64 + d + 32];
    const float t1 = buf[i1], t2 = buf[i2];
    buf[i1] = uaf(f2tf(t1*cosf(p1) - t2*sinf(p1)));
    buf[i2] = uaf(f2tf(t2*cosf(p2) + t1*sinf(p2)));
}

// ---------------------------------------------------------------------------
// Flash attention with TF32 MMA + ldmatrix for K and P fragments.
// Grid (N/64, B*H); 128 threads = 4 warps; each warp owns 16 Q rows.
// Ks[j][d] stride 68 (ldmatrix), Vs[j][d] stride 72 (scalar), Ps[r][j] stride 68.
// ---------------------------------------------------------------------------
#define KS_STRIDE 68
#define VS_STRIDE 72
#define PS_STRIDE 68
#define ATT_SMEM_FLOATS (64*KS_STRIDE + 64*VS_STRIDE + 64*PS_STRIDE)
#define ATT_SMEM_BYTES  (ATT_SMEM_FLOATS*4)

__global__ __launch_bounds__(128)
void attn_mma()
{
    extern __shared__ float sm[];
    float* Ks = sm;                                  // [64][68]  (j, d)
    float* Vs = sm + 64*KS_STRIDE;                   // [64][72]  (j, d)
    float* Ps = sm + 64*KS_STRIDE + 64*VS_STRIDE;    // [64][68]  (r, j)

    const int tid  = threadIdx.x;
    const int lane = tid & 31;
    const int wid  = tid >> 5;
    const int bh = blockIdx.y;
    const int m0 = blockIdx.x * 64;

    // --- Q fragments cached in registers (pre-rounded by rope; *0.125 exact) ---
    const float* Qb = g_Q + (size_t)bh * N_ * DH_;
    const int qr = m0 + wid*16 + (lane >> 2);
    unsigned qf[8][4];
#pragma unroll
    for (int ks = 0; ks < 8; ks++) {
        const int kk = ks*8 + (lane & 3);
        qf[ks][0] = fau(Qb[(size_t)qr*64      + kk  ] * 0.125f);
        qf[ks][1] = fau(Qb[(size_t)(qr+8)*64  + kk  ] * 0.125f);
        qf[ks][2] = fau(Qb[(size_t)qr*64      + kk+4] * 0.125f);
        qf[ks][3] = fau(Qb[(size_t)(qr+8)*64  + kk+4] * 0.125f);
    }

    // ldmatrix base addresses
    unsigned kAd[4], pAd;
#pragma unroll
    for (int p = 0; p < 4; p++)
        kAd[p] = sptr(&Ks[(p*16 + ((lane>>4)&1)*8 + (lane&7))*KS_STRIDE
                          + ((lane>>3)&1)*4]);
    pAd = sptr(&Ps[(wid*16 + ((lane>>3)&1)*8 + (lane&7))*PS_STRIDE
                   + (lane>>4)*4]);

    float mi[2] = {-1e30f, -1e30f};
    float li[2] = {0.f, 0.f};
    float o[8][4];
#pragma unroll
    for (int nt = 0; nt < 8; nt++)
#pragma unroll
        for (int v = 0; v < 4; v++) o[nt][v] = 0.f;

    for (int jt = 0; jt < N_/64; jt++) {
        const float* Kg = g_K + ((size_t)bh*N_ + jt*64) * DH_;
        const float* Vg = g_V + ((size_t)bh*N_ + jt*64) * DH_;
        __syncthreads();
        for (int t = tid; t < 1024; t += 128) {
            const int row = t >> 4, c4 = (t & 15) * 4;
            *(float4*)&Ks[row*KS_STRIDE + c4] = *(const float4*)(Kg + row*64 + c4);
            *(float4*)&Vs[row*VS_STRIDE + c4] = *(const float4*)(Vg + row*64 + c4);
        }
        __syncthreads();

        // --- S = (Q/8) K^T ---
        float s[8][4];
#pragma unroll
        for (int nt = 0; nt < 8; nt++)
#pragma unroll
            for (int v = 0; v < 4; v++) s[nt][v] = 0.f;
#pragma unroll
        for (int ks = 0; ks < 8; ks++) {
#pragma unroll
            for (int p = 0; p < 4; p++) {
                unsigned bb[4];
                ldsm4(bb[0], bb[1], bb[2], bb[3], kAd[p] + ks*32);
                mma8(s[2*p+0], qf[ks], &bb[0]);
                mma8(s[2*p+1], qf[ks], &bb[2]);
            }
        }

        // --- online softmax (2 rows per lane) ---
        float mx0 = -1e30f, mx1 = -1e30f;
#pragma unroll
        for (int nt = 0; nt < 8; nt++) {
            mx0 = fmaxf(mx0, fmaxf(s[nt][0], s[nt][1]));
            mx1 = fmaxf(mx1, fmaxf(s[nt][2], s[nt][3]));
        }
#pragma unroll
        for (int off = 1; off <= 2; off <<= 1) {
            mx0 = fmaxf(mx0, __shfl_xor_sync(0xffffffffu, mx0, off));
            mx1 = fmaxf(mx1, __shfl_xor_sync(0xffffffffu, mx1, off));
        }
        const float mn0 = fmaxf(mi[0], mx0);
        const float mn1 = fmaxf(mi[1], mx1);
        const float al0 = __expf(mi[0] - mn0);
        const float al1 = __expf(mi[1] - mn1);
        float rs0 = 0.f, rs1 = 0.f;
#pragma unroll
        for (int nt = 0; nt < 8; nt++) {
            float p0 = __expf(s[nt][0] - mn0);
            float p1 = __expf(s[nt][1] - mn0);
            float p2 = __expf(s[nt][2] - mn1);
            float p3 = __expf(s[nt][3] - mn1);
            s[nt][0] = p0; s[nt][1] = p1; s[nt][2] = p2; s[nt][3] = p3;
            rs0 += p0 + p1; rs1 += p2 + p3;
        }
#pragma unroll
        for (int off = 1; off <= 2; off <<= 1) {
            rs0 += __shfl_xor_sync(0xffffffffu, rs0, off);
            rs1 += __shfl_xor_sync(0xffffffffu, rs1, off);
        }
        li[0] = li[0]*al0 + rs0;  mi[0] = mn0;
        li[1] = li[1]*al1 + rs1;  mi[1] = mn1;
#pragma unroll
        for (int nt = 0; nt < 8; nt++) {
            o[nt][0] *= al0; o[nt][1] *= al0;
            o[nt][2] *= al1; o[nt][3] *= al1;
        }

        // --- store P (tf32) into per-warp-private rows of Ps ---
        {
            const int r0 = wid*16 + (lane >> 2);
#pragma unroll
            for (int nt = 0; nt < 8; nt++) {
                const int c = nt*8 + (lane & 3)*2;
                float2 lo, hi;
                lo.x = uaf(f2tf(s[nt][0])); lo.y = uaf(f2tf(s[nt][1]));
                hi.x = uaf(f2tf(s[nt][2])); hi.y = uaf(f2tf(s[nt][3]));
                *(float2*)&Ps[r0*PS_STRIDE + c]     = lo;
                *(float2*)&Ps[(r0+8)*PS_STRIDE + c] = hi;
            }
        }
        __syncwarp();

        // --- O += P @ V ---
#pragma unroll
        for (int ks = 0; ks < 8; ks++) {
            unsigned af[4];
            ldsm4(af[0], af[1], af[2], af[3], pAd + ks*32);
            const int kk = ks*8 + (lane & 3);
#pragma unroll
            for (int nt = 0; nt < 8; nt++) {
                unsigned bf[2];
                const int n = nt*8 + (lane >> 2);
                bf[0] = fau(Vs[kk*VS_STRIDE     + n]);
                bf[1] = fau(Vs[(kk+4)*VS_STRIDE + n]);
                mma8(o[nt], af, bf);
            }
        }
        __syncwarp();
    }

    // --- epilogue: normalize + write [b*n, h*64+d] ---
    const int b = bh >> 4, h = bh & 15;
    const float inv0 = 1.f / li[0];
    const float inv1 = 1.f / li[1];
    const int r0 = m0 + wid*16 + (lane >> 2);
#pragma unroll
    for (int nt = 0; nt < 8; nt++) {
        const int c = h*64 + nt*8 + (lane & 3)*2;
        float2 lo, hi;
        lo.x = o[nt][0]*inv0; lo.y = o[nt][1]*inv0;
        hi.x = o[nt][2]*inv1; hi.y = o[nt][3]*inv1;
        *(float2*)&g_A[((size_t)(b*N_ + r0))*D_ + c]     = lo;
        *(float2*)&g_A[((size_t)(b*N_ + r0 + 8))*D_ + c] = hi;
    }
}

// ---------------------------------------------------------------------------
extern "C" void kernel_launch(void* const* d_in, const int* in_sizes, int n_in,
                              void* d_out, int out_size)
{
    const float* x    = (const float*)d_in[0];
    const float* rot  = (const float*)d_in[1];
    const float* Wq   = (const float*)d_in[2];
    const float* Wkv  = (const float*)d_in[3];
    const float* Wout = (const float*)d_in[4];
    const float* bout = (const float*)d_in[5];
    float* out = (float*)d_out;

    float* gA = nullptr;
    cudaGetSymbolAddress((void**)&gA, g_A);
    cudaFuncSetAttribute(attn_mma,
                         cudaFuncAttributeMaxDynamicSharedMemorySize,
                         ATT_SMEM_BYTES);

    gemm_tf32<1><<<dim3(8, 64),  256>>>(x,  Wq,  nullptr, MTOT, 1024, 1024, nullptr);
    gemm_tf32<2><<<dim3(16, 64), 256>>>(x,  Wkv, nullptr, MTOT, 2048, 1024, nullptr);
    rope_kernel<<<(2*B_*H_*N_*32 + 255)/256, 256>>>(rot);
    attn_mma<<<dim3(N_/64, B_*H_), 128, ATT_SMEM_BYTES>>>();
    gemm_tf32<0><<<dim3(8, 64),  256>>>(gA, Wout, out, MTOT, 1024, 1024, bout);
}

// round 5
// speedup vs baseline: 3.9938x; 1.1225x over previous
#include <cuda_runtime.h>
#include <math.h>

#define H_   16
#define DH_  64
#define B_   4
#define N_   2048
#define D_   1024
#define MTOT (B_*N_)     // 8192

__device__ float g_Q[(size_t)B_*H_*N_*DH_];   // [b,h,n,d]
__device__ float g_K[(size_t)B_*H_*N_*DH_];
__device__ float g_V[(size_t)B_*H_*N_*DH_];
__device__ float g_A[(size_t)MTOT*D_];        // attention out, [b*n, h*d]

// ---------------------------------------------------------------------------
// helpers
// ---------------------------------------------------------------------------
__device__ __forceinline__ unsigned f2tf(float f) {
    unsigned u; asm("cvt.rna.tf32.f32 %0, %1;" : "=r"(u) : "f"(f)); return u;
}
__device__ __forceinline__ float uaf(unsigned u) { return __uint_as_float(u); }
__device__ __forceinline__ unsigned fau(float f) { return __float_as_uint(f); }
__device__ __forceinline__ unsigned sptr(const void* p) {
    return (unsigned)__cvta_generic_to_shared(p);
}
__device__ __forceinline__ void mma8(float* c, const unsigned* a, const unsigned* b) {
    asm volatile("mma.sync.aligned.m16n8k8.row.col.f32.tf32.tf32.f32 "
                 "{%0,%1,%2,%3}, {%4,%5,%6,%7}, {%8,%9}, {%0,%1,%2,%3};"
                 : "+f"(c[0]), "+f"(c[1]), "+f"(c[2]), "+f"(c[3])
                 : "r"(a[0]), "r"(a[1]), "r"(a[2]), "r"(a[3]),
                   "r"(b[0]), "r"(b[1]));
}
__device__ __forceinline__ void ldsm4(unsigned* r, unsigned addr) {
    asm volatile("ldmatrix.sync.aligned.m8n8.x4.shared.b16 {%0,%1,%2,%3}, [%4];"
                 : "=r"(r[0]), "=r"(r[1]), "=r"(r[2]), "=r"(r[3]) : "r"(addr));
}
__device__ __forceinline__ void cpa16(unsigned dst, const void* src) {
    asm volatile("cp.async.cg.shared.global [%0], [%1], 16;" :: "r"(dst), "l"(src));
}
#define CP_COMMIT() asm volatile("cp.async.commit_group;")
#define CP_WAIT0()  asm volatile("cp.async.wait_group 0;")

// ---------------------------------------------------------------------------
// TF32 GEMM, double-buffered smem, ldmatrix, 128x128 block, BK=16, 256 thr.
// MODE 0: C = acc + bias; MODE 1: scatter g_Q; MODE 2: K plain / V tf32-rounded
// ---------------------------------------------------------------------------
#define GST 20
#define GBUF (128*GST)       // floats per stage buffer
template<int MODE>
__global__ __launch_bounds__(256)
void gemm_tf32(const float* __restrict__ A, const float* __restrict__ Bm,
               float* __restrict__ C, int M, int N, int K,
               const float* __restrict__ bias)
{
    __shared__ float As[2*GBUF];
    __shared__ float Bs[2*GBUF];
    const int tid  = threadIdx.x;
    const int lane = tid & 31;
    const int wid  = tid >> 5;
    const int wm   = wid & 3;
    const int wn   = wid >> 2;
    const int m0 = blockIdx.y * 128, n0 = blockIdx.x * 128;

    float acc[2][8][4];
#pragma unroll
    for (int i = 0; i < 2; i++)
#pragma unroll
        for (int j = 0; j < 8; j++)
#pragma unroll
            for (int v = 0; v < 4; v++) acc[i][j][v] = 0.f;

    const int am  = tid >> 1,  ako = (tid & 1) * 8;
    const int bn  = tid & 127, bkh = (tid >> 7) * 8;
    const float* Ap = A  + (size_t)(m0 + am) * K + ako;
    const float* Bp = Bm + n0 + bn;

    float4 a0 = *(const float4*)(Ap);
    float4 a1 = *(const float4*)(Ap + 4);
    float br[8];
#pragma unroll
    for (int i = 0; i < 8; i++) br[i] = Bp[(size_t)(bkh + i) * N];

    unsigned aAd[2], bAd[4];
#pragma unroll
    for (int mt = 0; mt < 2; mt++)
        aAd[mt] = sptr(&As[(wm*32 + mt*16 + ((lane>>3)&1)*8 + (lane&7))*GST
                           + (lane>>4)*4]);
#pragma unroll
    for (int p = 0; p < 4; p++)
        bAd[p] = sptr(&Bs[(wn*64 + p*16 + ((lane>>4)&1)*8 + (lane&7))*GST
                          + ((lane>>3)&1)*4]);

    // store helper into stage buf
    auto stage = [&](int buf) {
        float* Ad = &As[buf*GBUF];
        float* Bd = &Bs[buf*GBUF];
        float4 w;
        w.x = uaf(f2tf(a0.x)); w.y = uaf(f2tf(a0.y));
        w.z = uaf(f2tf(a0.z)); w.w = uaf(f2tf(a0.w));
        *(float4*)&Ad[am*GST + ako] = w;
        w.x = uaf(f2tf(a1.x)); w.y = uaf(f2tf(a1.y));
        w.z = uaf(f2tf(a1.z)); w.w = uaf(f2tf(a1.w));
        *(float4*)&Ad[am*GST + ako + 4] = w;
        w.x = uaf(f2tf(br[0])); w.y = uaf(f2tf(br[1]));
        w.z = uaf(f2tf(br[2])); w.w = uaf(f2tf(br[3]));
        *(float4*)&Bd[bn*GST + bkh] = w;
        w.x = uaf(f2tf(br[4])); w.y = uaf(f2tf(br[5]));
        w.z = uaf(f2tf(br[6])); w.w = uaf(f2tf(br[7]));
        *(float4*)&Bd[bn*GST + bkh + 4] = w;
    };

    stage(0);
    __syncthreads();

    for (int k0 = 0; k0 < K; k0 += 16) {
        const int buf = (k0 >> 4) & 1;
        const unsigned boff = buf * GBUF * 4;
        const bool more = (k0 + 16 < K);
        if (more) {
            Ap += 16;
            a0 = *(const float4*)(Ap);
            a1 = *(const float4*)(Ap + 4);
#pragma unroll
            for (int i = 0; i < 8; i++)
                br[i] = Bp[(size_t)(k0 + 16 + bkh + i) * N];
        }

#pragma unroll
        for (int ks = 0; ks < 2; ks++) {
            unsigned af[2][4];
            ldsm4(af[0], aAd[0] + boff + ks*32);
            ldsm4(af[1], aAd[1] + boff + ks*32);
#pragma unroll
            for (int p = 0; p < 4; p++) {
                unsigned bb[4];
                ldsm4(bb, bAd[p] + boff + ks*32);
#pragma unroll
                for (int mt = 0; mt < 2; mt++) {
                    mma8(acc[mt][2*p+0], af[mt], &bb[0]);
                    mma8(acc[mt][2*p+1], af[mt], &bb[2]);
                }
            }
        }

        if (more) {
            stage(buf ^ 1);
            __syncthreads();
        }
    }

    // epilogue
#pragma unroll
    for (int mt = 0; mt < 2; mt++) {
        const int r0 = m0 + wm*32 + mt*16 + (lane >> 2);
#pragma unroll
        for (int nt = 0; nt < 8; nt++) {
            const int c = n0 + wn*64 + nt*8 + (lane & 3)*2;
#pragma unroll
            for (int half = 0; half < 2; half++) {
                const int row = r0 + half*8;
                float2 v;
                v.x = acc[mt][nt][half*2+0];
                v.y = acc[mt][nt][half*2+1];
                if (MODE == 0) {
                    v.x += bias[c]; v.y += bias[c+1];
                    *(float2*)&C[(size_t)row*N + c] = v;
                } else {
                    const int b = row >> 11, n = row & 2047;
                    if (MODE == 1) {
                        const int h = c >> 6, d = c & 63;
                        *(float2*)&g_Q[((size_t)(b*H_+h)*N_ + n)*DH_ + d] = v;
                    } else {
                        const bool isV = (c >= 1024);
                        if (isV) { v.x = uaf(f2tf(v.x)); v.y = uaf(f2tf(v.y)); }
                        float* base = isV ? g_V : g_K;
                        const int c2 = c & 1023;
                        const int h = c2 >> 6, d = c2 & 63;
                        *(float2*)&base[((size_t)(b*H_+h)*N_ + n)*DH_ + d] = v;
                    }
                }
            }
        }
    }
}

// ---------------------------------------------------------------------------
// RoPE on g_Q and g_K in place (pair (d, d+32)); stores tf32-rounded values.
// ---------------------------------------------------------------------------
__global__ void rope_kernel(const float* __restrict__ rot)
{
    const int idx = blockIdx.x * blockDim.x + threadIdx.x;
    const int half = B_*H_*N_*32;
    if (idx >= 2*half) return;
    float* buf = g_Q;
    int t = idx;
    if (t >= half) { buf = g_K; t -= half; }
    const int d    = t & 31;
    const int rest = t >> 5;
    const int n    = rest & (N_-1);
    const size_t i1 = (size_t)rest * 64 + d;
    const size_t i2 = i1 + 32;
    const float p1 = rot[n*64 + d];
    const float p2 = rot[n*64 + d + 32];
    const float t1 = buf[i1], t2 = buf[i2];
    buf[i1] = uaf(f2tf(t1*cosf(p1) - t2*sinf(p1)));
    buf[i2] = uaf(f2tf(t2*cosf(p2) + t1*sinf(p2)));
}

// ---------------------------------------------------------------------------
// Flash attention: 128-row blocks, 4 warps x 32 rows (2 m-tiles per warp),
// double-buffered cp.async K/V staging, ldmatrix K/P, exp2-based softmax.
// ---------------------------------------------------------------------------
#define KST 68
#define VST 72
#define PST 68
#define KS_FL (64*KST)          // 4352
#define VS_FL (64*VST)          // 4608
#define PS_FL (128*PST)         // 8704
#define ATT_FL (2*KS_FL + 2*VS_FL + PS_FL)   // 26624
#define ATT_BYTES (ATT_FL*4)                 // 106496

__global__ __launch_bounds__(128)
void attn_mma()
{
    extern __shared__ float sm[];
    float* KsB = sm;                      // 2 bufs of [64][68]
    float* VsB = sm + 2*KS_FL;            // 2 bufs of [64][72]
    float* Ps  = sm + 2*KS_FL + 2*VS_FL;  // [128][68]

    const int tid  = threadIdx.x;
    const int lane = tid & 31;
    const int wid  = tid >> 5;
    const int bh = blockIdx.y;
    const int m0 = blockIdx.x * 128;

    const unsigned ksU = sptr(KsB);
    const unsigned vsU = sptr(VsB);

    // Q fragments (pre-rounded tf32 in gmem); scale = 1/8 * log2(e) for exp2
    const float QSC = 0.125f * 1.4426950408889634f;
    const float* Qb = g_Q + (size_t)bh * N_ * DH_;
    const int qr = m0 + wid*32 + (lane >> 2);
    unsigned qf[2][8][4];
#pragma unroll
    for (int mt = 0; mt < 2; mt++) {
        const int r = qr + mt*16;
#pragma unroll
        for (int ks = 0; ks < 8; ks++) {
            const int kk = ks*8 + (lane & 3);
            qf[mt][ks][0] = fau(Qb[(size_t)r*64     + kk  ] * QSC);
            qf[mt][ks][1] = fau(Qb[(size_t)(r+8)*64 + kk  ] * QSC);
            qf[mt][ks][2] = fau(Qb[(size_t)r*64     + kk+4] * QSC);
            qf[mt][ks][3] = fau(Qb[(size_t)(r+8)*64 + kk+4] * QSC);
        }
    }

    // ldmatrix base addresses (buf 0)
    unsigned kAd[4], pAd[2];
#pragma unroll
    for (int p = 0; p < 4; p++)
        kAd[p] = ksU + ((p*16 + ((lane>>4)&1)*8 + (lane&7))*KST
                        + ((lane>>3)&1)*4) * 4;
#pragma unroll
    for (int mt = 0; mt < 2; mt++)
        pAd[mt] = sptr(&Ps[(wid*32 + mt*16 + ((lane>>3)&1)*8 + (lane&7))*PST
                           + (lane>>4)*4]);

    float mi[4] = {-1e30f, -1e30f, -1e30f, -1e30f};
    float li[4] = {0.f, 0.f, 0.f, 0.f};
    float o[2][8][4];
#pragma unroll
    for (int mt = 0; mt < 2; mt++)
#pragma unroll
        for (int nt = 0; nt < 8; nt++)
#pragma unroll
            for (int v = 0; v < 4; v++) o[mt][nt][v] = 0.f;

    const float* KgB = g_K + (size_t)bh * N_ * DH_;
    const float* VgB = g_V + (size_t)bh * N_ * DH_;

    // staging: 8 x cp.async 16B per thread per tensor
    auto issue = [&](int jt, int buf) {
        const float* Kg = KgB + (size_t)jt * 64 * 64;
        const float* Vg = VgB + (size_t)jt * 64 * 64;
        const unsigned kd = ksU + buf * (KS_FL*4);
        const unsigned vd = vsU + buf * (VS_FL*4);
#pragma unroll
        for (int it = 0; it < 8; it++) {
            const int t = tid + it*128;
            const int row = t >> 4, c4 = (t & 15) * 4;
            cpa16(kd + (row*KST + c4)*4, Kg + row*64 + c4);
            cpa16(vd + (row*VST + c4)*4, Vg + row*64 + c4);
        }
        CP_COMMIT();
    };

    issue(0, 0);

    for (int jt = 0; jt < N_/64; jt++) {
        const int buf = jt & 1;
        CP_WAIT0();
        __syncthreads();
        if (jt + 1 < N_/64) issue(jt + 1, buf ^ 1);

        const unsigned kOff = buf * (KS_FL*4);
        // --- S = (Q*scale) K^T ---
        float s[2][8][4];
#pragma unroll
        for (int mt = 0; mt < 2; mt++)
#pragma unroll
            for (int nt = 0; nt < 8; nt++)
#pragma unroll
                for (int v = 0; v < 4; v++) s[mt][nt][v] = 0.f;
#pragma unroll
        for (int ks = 0; ks < 8; ks++) {
#pragma unroll
            for (int p = 0; p < 4; p++) {
                unsigned bb[4];
                ldsm4(bb, kAd[p] + kOff + ks*32);
                mma8(s[0][2*p+0], qf[0][ks], &bb[0]);
                mma8(s[0][2*p+1], qf[0][ks], &bb[2]);
                mma8(s[1][2*p+0], qf[1][ks], &bb[0]);
                mma8(s[1][2*p+1], qf[1][ks], &bb[2]);
            }
        }

        // --- online softmax per m-tile (base-2) ---
#pragma unroll
        for (int mt = 0; mt < 2; mt++) {
            float mx0 = -1e30f, mx1 = -1e30f;
#pragma unroll
            for (int nt = 0; nt < 8; nt++) {
                mx0 = fmaxf(mx0, fmaxf(s[mt][nt][0], s[mt][nt][1]));
                mx1 = fmaxf(mx1, fmaxf(s[mt][nt][2], s[mt][nt][3]));
            }
#pragma unroll
            for (int off = 1; off <= 2; off <<= 1) {
                mx0 = fmaxf(mx0, __shfl_xor_sync(0xffffffffu, mx0, off));
                mx1 = fmaxf(mx1, __shfl_xor_sync(0xffffffffu, mx1, off));
            }
            const float mn0 = fmaxf(mi[mt*2+0], mx0);
            const float mn1 = fmaxf(mi[mt*2+1], mx1);
            const float al0 = exp2f(mi[mt*2+0] - mn0);
            const float al1 = exp2f(mi[mt*2+1] - mn1);
            float rs0 = 0.f, rs1 = 0.f;
#pragma unroll
            for (int nt = 0; nt < 8; nt++) {
                float p0 = exp2f(s[mt][nt][0] - mn0);
                float p1 = exp2f(s[mt][nt][1] - mn0);
                float p2 = exp2f(s[mt][nt][2] - mn1);
                float p3 = exp2f(s[mt][nt][3] - mn1);
                s[mt][nt][0] = p0; s[mt][nt][1] = p1;
                s[mt][nt][2] = p2; s[mt][nt][3] = p3;
                rs0 += p0 + p1; rs1 += p2 + p3;
            }
#pragma unroll
            for (int off = 1; off <= 2; off <<= 1) {
                rs0 += __shfl_xor_sync(0xffffffffu, rs0, off);
                rs1 += __shfl_xor_sync(0xffffffffu, rs1, off);
            }
            li[mt*2+0] = li[mt*2+0]*al0 + rs0;  mi[mt*2+0] = mn0;
            li[mt*2+1] = li[mt*2+1]*al1 + rs1;  mi[mt*2+1] = mn1;
#pragma unroll
            for (int nt = 0; nt < 8; nt++) {
                o[mt][nt][0] *= al0; o[mt][nt][1] *= al0;
                o[mt][nt][2] *= al1; o[mt][nt][3] *= al1;
            }
            // store P (tf32) into warp-private rows of Ps
            const int r0 = wid*32 + mt*16 + (lane >> 2);
#pragma unroll
            for (int nt = 0; nt < 8; nt++) {
                const int c = nt*8 + (lane & 3)*2;
                float2 lo, hi;
                lo.x = uaf(f2tf(s[mt][nt][0])); lo.y = uaf(f2tf(s[mt][nt][1]));
                hi.x = uaf(f2tf(s[mt][nt][2])); hi.y = uaf(f2tf(s[mt][nt][3]));
                *(float2*)&Ps[r0*PST + c]     = lo;
                *(float2*)&Ps[(r0+8)*PST + c] = hi;
            }
        }
        __syncwarp();

        // --- O += P @ V ---
        const float* Vp = VsB + buf * VS_FL;
#pragma unroll
        for (int ks = 0; ks < 8; ks++) {
            unsigned af0[4], af1[4];
            ldsm4(af0, pAd[0] + ks*32);
            ldsm4(af1, pAd[1] + ks*32);
            const int kk = ks*8 + (lane & 3);
#pragma unroll
            for (int nt = 0; nt < 8; nt++) {
                unsigned bf[2];
                const int n = nt*8 + (lane >> 2);
                bf[0] = fau(Vp[kk*VST     + n]);
                bf[1] = fau(Vp[(kk+4)*VST + n]);
                mma8(o[0][nt], af0, bf);
                mma8(o[1][nt], af1, bf);
            }
        }
        __syncwarp();
    }

    // --- epilogue: normalize + write [b*n, h*64+d] ---
    const int b = bh >> 4, h = bh & 15;
#pragma unroll
    for (int mt = 0; mt < 2; mt++) {
        const float inv0 = 1.f / li[mt*2+0];
        const float inv1 = 1.f / li[mt*2+1];
        const int r0 = m0 + wid*32 + mt*16 + (lane >> 2);
#pragma unroll
        for (int nt = 0; nt < 8; nt++) {
            const int c = h*64 + nt*8 + (lane & 3)*2;
            float2 lo, hi;
            lo.x = o[mt][nt][0]*inv0; lo.y = o[mt][nt][1]*inv0;
            hi.x = o[mt][nt][2]*inv1; hi.y = o[mt][nt][3]*inv1;
            *(float2*)&g_A[((size_t)(b*N_ + r0))*D_ + c]     = lo;
            *(float2*)&g_A[((size_t)(b*N_ + r0 + 8))*D_ + c] = hi;
        }
    }
}

// ---------------------------------------------------------------------------
extern "C" void kernel_launch(void* const* d_in, const int* in_sizes, int n_in,
                              void* d_out, int out_size)
{
    const float* x    = (const float*)d_in[0];
    const float* rot  = (const float*)d_in[1];
    const float* Wq   = (const float*)d_in[2];
    const float* Wkv  = (const float*)d_in[3];
    const float* Wout = (const float*)d_in[4];
    const float* bout = (const float*)d_in[5];
    float* out = (float*)d_out;

    float* gA = nullptr;
    cudaGetSymbolAddress((void**)&gA, g_A);
    cudaFuncSetAttribute(attn_mma,
                         cudaFuncAttributeMaxDynamicSharedMemorySize,
                         ATT_BYTES);

    gemm_tf32<1><<<dim3(8, 64),  256>>>(x,  Wq,  nullptr, MTOT, 1024, 1024, nullptr);
    gemm_tf32<2><<<dim3(16, 64), 256>>>(x,  Wkv, nullptr, MTOT, 2048, 1024, nullptr);
    rope_kernel<<<(2*B_*H_*N_*32 + 255)/256, 256>>>(rot);
    attn_mma<<<dim3(N_/128, B_*H_), 128, ATT_BYTES>>>();
    gemm_tf32<0><<<dim3(8, 64),  256>>>(gA, Wout, out, MTOT, 1024, 1024, bout);
}

// round 7
// speedup vs baseline: 6.2004x; 1.5525x over previous
#include <cuda_runtime.h>
#include <cuda_fp16.h>
#include <math.h>

#define H_   16
#define DH_  64
#define B_   4
#define N_   2048
#define D_   1024
#define MTOT (B_*N_)     // 8192

__device__ __half g_Qh[(size_t)B_*H_*N_*DH_];   // [b,h,n,d]
__device__ __half g_Kh[(size_t)B_*H_*N_*DH_];
__device__ __half g_Vh[(size_t)B_*H_*N_*DH_];
__device__ __half g_Ah[(size_t)MTOT*D_];        // attention out, [b*n, h*d]

// ---------------------------------------------------------------------------
// helpers
// ---------------------------------------------------------------------------
__device__ __forceinline__ unsigned h2u(__half2 h) { return *(unsigned*)&h; }
__device__ __forceinline__ unsigned sptr(const void* p) {
    return (unsigned)__cvta_generic_to_shared(p);
}
__device__ __forceinline__ void mma16(float* c, const unsigned* a, const unsigned* b) {
    asm volatile("mma.sync.aligned.m16n8k16.row.col.f32.f16.f16.f32 "
                 "{%0,%1,%2,%3}, {%4,%5,%6,%7}, {%8,%9}, {%0,%1,%2,%3};"
                 : "+f"(c[0]), "+f"(c[1]), "+f"(c[2]), "+f"(c[3])
                 : "r"(a[0]), "r"(a[1]), "r"(a[2]), "r"(a[3]),
                   "r"(b[0]), "r"(b[1]));
}
__device__ __forceinline__ void ldsm4(unsigned* r, unsigned addr) {
    asm volatile("ldmatrix.sync.aligned.m8n8.x4.shared.b16 {%0,%1,%2,%3}, [%4];"
                 : "=r"(r[0]), "=r"(r[1]), "=r"(r[2]), "=r"(r[3]) : "r"(addr));
}
__device__ __forceinline__ void ldsm4t(unsigned* r, unsigned addr) {
    asm volatile("ldmatrix.sync.aligned.m8n8.x4.trans.shared.b16 {%0,%1,%2,%3}, [%4];"
                 : "=r"(r[0]), "=r"(r[1]), "=r"(r[2]), "=r"(r[3]) : "r"(addr));
}
__device__ __forceinline__ void cpa16(unsigned dst, const void* src) {
    asm volatile("cp.async.cg.shared.global [%0], [%1], 16;" :: "r"(dst), "l"(src));
}
#define CP_COMMIT() asm volatile("cp.async.commit_group;")
#define CP_WAIT0()  asm volatile("cp.async.wait_group 0;")

// ---------------------------------------------------------------------------
// FP16 GEMM (fp32 accum), double-buffered smem, ldmatrix, 128x128, BK=16.
// MODE 0: C = acc + bias (fp32 out); MODE 1: fp16 -> g_Qh; MODE 2: g_Kh/g_Vh
// ---------------------------------------------------------------------------
#define AST 24                      // halves per smem row
#define GBUFH (128*AST)             // halves per stage buffer
template<int MODE, typename TA>
__global__ __launch_bounds__(256)
void gemm_h(const TA* __restrict__ A, const float* __restrict__ Bm,
            float* __restrict__ C, int M, int N, int K,
            const float* __restrict__ bias)
{
    __shared__ __half As[2*GBUFH];
    __shared__ __half Bs[2*GBUFH];
    const int tid  = threadIdx.x;
    const int lane = tid & 31;
    const int wid  = tid >> 5;
    const int wm   = wid & 3;
    const int wn   = wid >> 2;
    const int m0 = blockIdx.y * 128, n0 = blockIdx.x * 128;

    float acc[2][8][4];
#pragma unroll
    for (int i = 0; i < 2; i++)
#pragma unroll
        for (int j = 0; j < 8; j++)
#pragma unroll
            for (int v = 0; v < 4; v++) acc[i][j][v] = 0.f;

    const int am  = tid >> 1,  ako = (tid & 1) * 8;
    const int bn  = tid & 127, bkh = (tid >> 7) * 8;
    const TA* Ap = A + (size_t)(m0 + am) * K + ako;
    const float* Bp = Bm + n0 + bn;

    float4 a0, a1; uint4 ah;
    if constexpr (sizeof(TA) == 4) {
        a0 = *(const float4*)(Ap);
        a1 = *(const float4*)(Ap + 4);
    } else {
        ah = *(const uint4*)(Ap);
    }
    float br[8];
#pragma unroll
    for (int i = 0; i < 8; i++) br[i] = Bp[(size_t)(bkh + i) * N];

    // fragment addresses (buf 0)
    unsigned aAd[2], bAd[4];
#pragma unroll
    for (int mt = 0; mt < 2; mt++)
        aAd[mt] = sptr(&As[(wm*32 + mt*16 + (lane & 15))*AST + (lane >> 4)*8]);
#pragma unroll
    for (int p = 0; p < 4; p++)
        bAd[p] = sptr(&Bs[(wn*64 + p*16 + (lane & 7) + (lane >> 4)*8)*AST
                          + ((lane >> 3) & 1)*8]);

    auto stage = [&](int buf) {
        __half* Ad = &As[buf*GBUFH];
        __half* Bd = &Bs[buf*GBUFH];
        uint4 w;
        if constexpr (sizeof(TA) == 4) {
            w.x = h2u(__floats2half2_rn(a0.x, a0.y));
            w.y = h2u(__floats2half2_rn(a0.z, a0.w));
            w.z = h2u(__floats2half2_rn(a1.x, a1.y));
            w.w = h2u(__floats2half2_rn(a1.z, a1.w));
        } else {
            w = ah;
        }
        *(uint4*)&Ad[am*AST + ako] = w;
        w.x = h2u(__floats2half2_rn(br[0], br[1]));
        w.y = h2u(__floats2half2_rn(br[2], br[3]));
        w.z = h2u(__floats2half2_rn(br[4], br[5]));
        w.w = h2u(__floats2half2_rn(br[6], br[7]));
        *(uint4*)&Bd[bn*AST + bkh] = w;
    };

    stage(0);
    __syncthreads();

    for (int k0 = 0; k0 < K; k0 += 16) {
        const int buf = (k0 >> 4) & 1;
        const unsigned boff = buf * GBUFH * 2;
        const bool more = (k0 + 16 < K);
        if (more) {
            Ap += 16;
            if constexpr (sizeof(TA) == 4) {
                a0 = *(const float4*)(Ap);
                a1 = *(const float4*)(Ap + 4);
            } else {
                ah = *(const uint4*)(Ap);
            }
#pragma unroll
            for (int i = 0; i < 8; i++)
                br[i] = Bp[(size_t)(k0 + 16 + bkh + i) * N];
        }

        unsigned af[2][4];
        ldsm4(af[0], aAd[0] + boff);
        ldsm4(af[1], aAd[1] + boff);
#pragma unroll
        for (int p = 0; p < 4; p++) {
            unsigned bb[4];
            ldsm4(bb, bAd[p] + boff);
#pragma unroll
            for (int mt = 0; mt < 2; mt++) {
                mma16(acc[mt][2*p+0], af[mt], &bb[0]);
                mma16(acc[mt][2*p+1], af[mt], &bb[2]);
            }
        }

        if (more) {
            stage(buf ^ 1);
            __syncthreads();
        }
    }

    // epilogue
#pragma unroll
    for (int mt = 0; mt < 2; mt++) {
        const int r0 = m0 + wm*32 + mt*16 + (lane >> 2);
#pragma unroll
        for (int nt = 0; nt < 8; nt++) {
            const int c = n0 + wn*64 + nt*8 + (lane & 3)*2;
#pragma unroll
            for (int half = 0; half < 2; half++) {
                const int row = r0 + half*8;
                float vx = acc[mt][nt][half*2+0];
                float vy = acc[mt][nt][half*2+1];
                if (MODE == 0) {
                    float2 v; v.x = vx + bias[c]; v.y = vy + bias[c+1];
                    *(float2*)&C[(size_t)row*N + c] = v;
                } else {
                    const int b = row >> 11, n = row & 2047;
                    __half2 hv = __floats2half2_rn(vx, vy);
                    if (MODE == 1) {
                        const int h = c >> 6, d = c & 63;
                        *(__half2*)&g_Qh[((size_t)(b*H_+h)*N_ + n)*DH_ + d] = hv;
                    } else {
                        __half* base = (c >= 1024) ? g_Vh : g_Kh;
                        const int c2 = c & 1023;
                        const int h = c2 >> 6, d = c2 & 63;
                        *(__half2*)&base[((size_t)(b*H_+h)*N_ + n)*DH_ + d] = hv;
                    }
                }
            }
        }
    }
}

// ---------------------------------------------------------------------------
// RoPE on g_Qh and g_Kh in place (pair (d, d+32)), fp32 math, rn rounding.
// ---------------------------------------------------------------------------
__global__ void rope_kernel(const float* __restrict__ rot)
{
    const int idx = blockIdx.x * blockDim.x + threadIdx.x;
    const int half = B_*H_*N_*32;
    if (idx >= 2*half) return;
    __half* buf = g_Qh;
    int t = idx;
    if (t >= half) { buf = g_Kh; t -= half; }
    const int d    = t & 31;
    const int rest = t >> 5;
    const int n    = rest & (N_-1);
    const size_t i1 = (size_t)rest * 64 + d;
    const size_t i2 = i1 + 32;
    const float p1 = rot[n*64 + d];
    const float p2 = rot[n*64 + d + 32];
    const float t1 = __half2float(buf[i1]);
    const float t2 = __half2float(buf[i2]);
    buf[i1] = __float2half_rn(t1*cosf(p1) - t2*sinf(p1));
    buf[i2] = __float2half_rn(t2*cosf(p2) + t1*sinf(p2));
}

// ---------------------------------------------------------------------------
// Flash attention (fp16 mma): 128-row blocks, 4 warps x 32 rows,
// double-buffered cp.async K/V, ldmatrix K/P, ldmatrix.trans V, exp2 softmax.
// ---------------------------------------------------------------------------
#define KST 72
#define VST 72
#define PST 72
#define KS_FL (64*KST)          // halves
#define VS_FL (64*VST)
#define PS_FL (128*PST)
#define ATT_BYTES ((2*KS_FL + 2*VS_FL + PS_FL)*2)   // 55296

__global__ __launch_bounds__(128)
void attn_mma()
{
    extern __shared__ __half smh[];
    __half* KsB = smh;                      // 2 bufs [64][72]
    __half* VsB = smh + 2*KS_FL;            // 2 bufs [64][72]
    __half* Ps  = smh + 2*KS_FL + 2*VS_FL;  // [128][72]

    const int tid  = threadIdx.x;
    const int lane = tid & 31;
    const int wid  = tid >> 5;
    const int bh = blockIdx.y;
    const int m0 = blockIdx.x * 128;

    const unsigned ksU = sptr(KsB);
    const unsigned vsU = sptr(VsB);

    // Q fragments, scaled by 1/8*log2(e), rn-rounded back to fp16
    const float QSC = 0.125f * 1.4426950408889634f;
    const __half* Qb = g_Qh + (size_t)bh * N_ * DH_;
    const int qr = m0 + wid*32 + (lane >> 2);
    unsigned qf[2][4][4];
#pragma unroll
    for (int mt = 0; mt < 2; mt++) {
        const int r = qr + mt*16;
#pragma unroll
        for (int ks = 0; ks < 4; ks++) {
            const int kk = ks*16 + (lane & 3)*2;
#pragma unroll
            for (int v = 0; v < 4; v++) {
                const int rr = r + (v & 1)*8;
                const int cc = kk + (v >> 1)*8;
                float2 f = __half22float2(*(const __half2*)&Qb[(size_t)rr*64 + cc]);
                qf[mt][ks][v] = h2u(__floats2half2_rn(f.x*QSC, f.y*QSC));
            }
        }
    }

    // ldmatrix addresses (buf 0)
    unsigned kAd[4], pAd[2], vAd[4];
#pragma unroll
    for (int p = 0; p < 4; p++)
        kAd[p] = ksU + ((p*16 + (lane & 7) + (lane >> 4)*8)*KST
                        + ((lane >> 3) & 1)*8) * 2;
#pragma unroll
    for (int mt = 0; mt < 2; mt++)
        pAd[mt] = sptr(&Ps[(wid*32 + mt*16 + (lane & 15))*PST + (lane >> 4)*8]);
#pragma unroll
    for (int dv = 0; dv < 4; dv++)
        vAd[dv] = vsU + (((lane & 15))*VST + dv*16 + (lane >> 4)*8) * 2;

    float mi[4] = {-1e30f, -1e30f, -1e30f, -1e30f};
    float li[4] = {0.f, 0.f, 0.f, 0.f};
    float o[2][8][4];
#pragma unroll
    for (int mt = 0; mt < 2; mt++)
#pragma unroll
        for (int nt = 0; nt < 8; nt++)
#pragma unroll
            for (int v = 0; v < 4; v++) o[mt][nt][v] = 0.f;

    const __half* KgB = g_Kh + (size_t)bh * N_ * DH_;
    const __half* VgB = g_Vh + (size_t)bh * N_ * DH_;

    auto issue = [&](int jt, int buf) {
        const __half* Kg = KgB + (size_t)jt * 64 * 64;
        const __half* Vg = VgB + (size_t)jt * 64 * 64;
        const unsigned kd = ksU + buf * (KS_FL*2);
        const unsigned vd = vsU + buf * (VS_FL*2);
#pragma unroll
        for (int it = 0; it < 4; it++) {
            const int t = tid + it*128;
            const int row = t >> 3, c8 = (t & 7) * 8;
            cpa16(kd + (row*KST + c8)*2, Kg + row*64 + c8);
            cpa16(vd + (row*VST + c8)*2, Vg + row*64 + c8);
        }
        CP_COMMIT();
    };

    issue(0, 0);

    for (int jt = 0; jt < N_/64; jt++) {
        const int buf = jt & 1;
        CP_WAIT0();
        __syncthreads();
        if (jt + 1 < N_/64) issue(jt + 1, buf ^ 1);

        const unsigned kOff = buf * (KS_FL*2);
        // --- S = (Q*scale) K^T ---
        float s[2][8][4];
#pragma unroll
        for (int mt = 0; mt < 2; mt++)
#pragma unroll
            for (int nt = 0; nt < 8; nt++)
#pragma unroll
                for (int v = 0; v < 4; v++) s[mt][nt][v] = 0.f;
#pragma unroll
        for (int ks = 0; ks < 4; ks++) {
#pragma unroll
            for (int p = 0; p < 4; p++) {
                unsigned bb[4];
                ldsm4(bb, kAd[p] + kOff + ks*32);
                mma16(s[0][2*p+0], qf[0][ks], &bb[0]);
                mma16(s[0][2*p+1], qf[0][ks], &bb[2]);
                mma16(s[1][2*p+0], qf[1][ks], &bb[0]);
                mma16(s[1][2*p+1], qf[1][ks], &bb[2]);
            }
        }

        // --- online softmax (base-2) ---
#pragma unroll
        for (int mt = 0; mt < 2; mt++) {
            float mx0 = -1e30f, mx1 = -1e30f;
#pragma unroll
            for (int nt = 0; nt < 8; nt++) {
                mx0 = fmaxf(mx0, fmaxf(s[mt][nt][0], s[mt][nt][1]));
                mx1 = fmaxf(mx1, fmaxf(s[mt][nt][2], s[mt][nt][3]));
            }
#pragma unroll
            for (int off = 1; off <= 2; off <<= 1) {
                mx0 = fmaxf(mx0, __shfl_xor_sync(0xffffffffu, mx0, off));
                mx1 = fmaxf(mx1, __shfl_xor_sync(0xffffffffu, mx1, off));
            }
            const float mn0 = fmaxf(mi[mt*2+0], mx0);
            const float mn1 = fmaxf(mi[mt*2+1], mx1);
            const float al0 = exp2f(mi[mt*2+0] - mn0);
            const float al1 = exp2f(mi[mt*2+1] - mn1);
            float rs0 = 0.f, rs1 = 0.f;
            const int r0 = wid*32 + mt*16 + (lane >> 2);
#pragma unroll
            for (int nt = 0; nt < 8; nt++) {
                float p0 = exp2f(s[mt][nt][0] - mn0);
                float p1 = exp2f(s[mt][nt][1] - mn0);
                float p2 = exp2f(s[mt][nt][2] - mn1);
                float p3 = exp2f(s[mt][nt][3] - mn1);
                rs0 += p0 + p1; rs1 += p2 + p3;
                const int c = nt*8 + (lane & 3)*2;
                *(__half2*)&Ps[r0*PST + c]     = __floats2half2_rn(p0, p1);
                *(__half2*)&Ps[(r0+8)*PST + c] = __floats2half2_rn(p2, p3);
            }
#pragma unroll
            for (int off = 1; off <= 2; off <<= 1) {
                rs0 += __shfl_xor_sync(0xffffffffu, rs0, off);
                rs1 += __shfl_xor_sync(0xffffffffu, rs1, off);
            }
            li[mt*2+0] = li[mt*2+0]*al0 + rs0;  mi[mt*2+0] = mn0;
            li[mt*2+1] = li[mt*2+1]*al1 + rs1;  mi[mt*2+1] = mn1;
#pragma unroll
            for (int nt = 0; nt < 8; nt++) {
                o[mt][nt][0] *= al0; o[mt][nt][1] *= al0;
                o[mt][nt][2] *= al1; o[mt][nt][3] *= al1;
            }
        }
        __syncwarp();

        // --- O += P @ V ---
        const unsigned vOff = buf * (VS_FL*2);
#pragma unroll
        for (int ks = 0; ks < 4; ks++) {
            unsigned af0[4], af1[4];
            ldsm4(af0, pAd[0] + ks*32);
            ldsm4(af1, pAd[1] + ks*32);
#pragma unroll
            for (int dv = 0; dv < 4; dv++) {
                unsigned bb[4];
                ldsm4t(bb, vAd[dv] + vOff + ks*(16*VST*2));
                mma16(o[0][2*dv+0], af0, &bb[0]);
                mma16(o[0][2*dv+1], af0, &bb[2]);
                mma16(o[1][2*dv+0], af1, &bb[0]);
                mma16(o[1][2*dv+1], af1, &bb[2]);
            }
        }
        __syncwarp();
    }

    // --- epilogue: normalize + fp16 write [b*n, h*64+d] ---
    const int b = bh >> 4, h = bh & 15;
#pragma unroll
    for (int mt = 0; mt < 2; mt++) {
        const float inv0 = 1.f / li[mt*2+0];
        const float inv1 = 1.f / li[mt*2+1];
        const int r0 = m0 + wid*32 + mt*16 + (lane >> 2);
#pragma unroll
        for (int nt = 0; nt < 8; nt++) {
            const int c = h*64 + nt*8 + (lane & 3)*2;
            *(__half2*)&g_Ah[((size_t)(b*N_ + r0))*D_ + c] =
                __floats2half2_rn(o[mt][nt][0]*inv0, o[mt][nt][1]*inv0);
            *(__half2*)&g_Ah[((size_t)(b*N_ + r0 + 8))*D_ + c] =
                __floats2half2_rn(o[mt][nt][2]*inv1, o[mt][nt][3]*inv1);
        }
    }
}

// ---------------------------------------------------------------------------
extern "C" void kernel_launch(void* const* d_in, const int* in_sizes, int n_in,
                              void* d_out, int out_size)
{
    const float* x    = (const float*)d_in[0];
    const float* rot  = (const float*)d_in[1];
    const float* Wq   = (const float*)d_in[2];
    const float* Wkv  = (const float*)d_in[3];
    const float* Wout = (const float*)d_in[4];
    const float* bout = (const float*)d_in[5];
    float* out = (float*)d_out;

    __half* gA = nullptr;
    cudaGetSymbolAddress((void**)&gA, g_Ah);
    cudaFuncSetAttribute(attn_mma,
                         cudaFuncAttributeMaxDynamicSharedMemorySize,
                         ATT_BYTES);

    gemm_h<1, float><<<dim3(8, 64),  256>>>(x,  Wq,  nullptr, MTOT, 1024, 1024, nullptr);
    gemm_h<2, float><<<dim3(16, 64), 256>>>(x,  Wkv, nullptr, MTOT, 2048, 1024, nullptr);
    rope_kernel<<<(2*B_*H_*N_*32 + 255)/256, 256>>>(rot);
    attn_mma<<<dim3(N_/128, B_*H_), 128, ATT_BYTES>>>();
    gemm_h<0, __half><<<dim3(8, 64), 256>>>(gA, Wout, out, MTOT, 1024, 1024, bout);
}

// round 9
// speedup vs baseline: 7.6082x; 1.2270x over previous
#include <cuda_runtime.h>
#include <cuda_fp16.h>
#include <math.h>

#define H_   16
#define DH_  64
#define B_   4
#define N_   2048
#define D_   1024
#define MTOT (B_*N_)     // 8192

__device__ __half g_Qh[(size_t)B_*H_*N_*DH_];   // [b,h,n,d]
__device__ __half g_Kh[(size_t)B_*H_*N_*DH_];
__device__ __half g_Vh[(size_t)B_*H_*N_*DH_];
__device__ __half g_Ah[(size_t)MTOT*D_];        // attention out, [b*n, h*d]
__device__ __half g_Xh[(size_t)MTOT*D_];        // x in fp16
__device__ __half g_Wqh[(size_t)D_*D_];
__device__ __half g_Wkvh[(size_t)D_*2*D_];
__device__ __half g_Woh[(size_t)D_*D_];

// ---------------------------------------------------------------------------
// helpers
// ---------------------------------------------------------------------------
__device__ __forceinline__ unsigned h2u(__half2 h) { return *(unsigned*)&h; }
__device__ __forceinline__ unsigned sptr(const void* p) {
    return (unsigned)__cvta_generic_to_shared(p);
}
__device__ __forceinline__ void mma16(float* c, const unsigned* a, const unsigned* b) {
    asm volatile("mma.sync.aligned.m16n8k16.row.col.f32.f16.f16.f32 "
                 "{%0,%1,%2,%3}, {%4,%5,%6,%7}, {%8,%9}, {%0,%1,%2,%3};"
                 : "+f"(c[0]), "+f"(c[1]), "+f"(c[2]), "+f"(c[3])
                 : "r"(a[0]), "r"(a[1]), "r"(a[2]), "r"(a[3]),
                   "r"(b[0]), "r"(b[1]));
}
__device__ __forceinline__ void ldsm4(unsigned* r, unsigned addr) {
    asm volatile("ldmatrix.sync.aligned.m8n8.x4.shared.b16 {%0,%1,%2,%3}, [%4];"
                 : "=r"(r[0]), "=r"(r[1]), "=r"(r[2]), "=r"(r[3]) : "r"(addr));
}
__device__ __forceinline__ void ldsm4t(unsigned* r, unsigned addr) {
    asm volatile("ldmatrix.sync.aligned.m8n8.x4.trans.shared.b16 {%0,%1,%2,%3}, [%4];"
                 : "=r"(r[0]), "=r"(r[1]), "=r"(r[2]), "=r"(r[3]) : "r"(addr));
}
__device__ __forceinline__ void cpa16(unsigned dst, const void* src) {
    asm volatile("cp.async.cg.shared.global [%0], [%1], 16;" :: "r"(dst), "l"(src));
}
#define CP_COMMIT() asm volatile("cp.async.commit_group;")
#define CP_WAIT0()  asm volatile("cp.async.wait_group 0;")

// ---------------------------------------------------------------------------
// f32 -> f16 conversion (vector4)
// ---------------------------------------------------------------------------
__global__ void cvt_h(const float4* __restrict__ src, uint2* __restrict__ dst, int n4)
{
    for (int i = blockIdx.x * blockDim.x + threadIdx.x; i < n4;
         i += gridDim.x * blockDim.x) {
        float4 v = src[i];
        uint2 o;
        o.x = h2u(__floats2half2_rn(v.x, v.y));
        o.y = h2u(__floats2half2_rn(v.z, v.w));
        dst[i] = o;
    }
}

// ---------------------------------------------------------------------------
// FP16 GEMM (fp32 accum): 128x128 tile, BK=32, cp.async double buffer.
// A fp16 [M][K] (ldmatrix), B fp16 [K][N] staged [k][n] (ldmatrix.trans).
// MODE 0: C = acc + bias (fp32); MODE 1: fp16 -> g_Qh; MODE 2: g_Kh/g_Vh
// ---------------------------------------------------------------------------
#define AST 40                       // 32 + 8 pad (halves)
#define BST 136                      // 128 + 8 pad (halves)
#define ABUF (128*AST)               // halves per A stage
#define BBUF (32*BST)                // halves per B stage
template<int MODE>
__global__ __launch_bounds__(256)
void gemm_h(const __half* __restrict__ A, const __half* __restrict__ Bm,
            float* __restrict__ C, int M, int N, int K,
            const float* __restrict__ bias)
{
    __shared__ __half As[2*ABUF];
    __shared__ __half Bs[2*BBUF];
    const int tid  = threadIdx.x;
    const int lane = tid & 31;
    const int wid  = tid >> 5;
    const int wm   = wid & 3;
    const int wn   = wid >> 2;
    const int m0 = blockIdx.y * 128, n0 = blockIdx.x * 128;

    const unsigned asU = sptr(As);
    const unsigned bsU = sptr(Bs);

    float acc[2][8][4];
#pragma unroll
    for (int i = 0; i < 2; i++)
#pragma unroll
        for (int j = 0; j < 8; j++)
#pragma unroll
            for (int v = 0; v < 4; v++) acc[i][j][v] = 0.f;

    // fragment addresses (buf 0)
    unsigned aAd[2], bAd[4];
#pragma unroll
    for (int mt = 0; mt < 2; mt++)
        aAd[mt] = asU + ((wm*32 + mt*16 + (lane & 15))*AST + (lane >> 4)*8) * 2;
#pragma unroll
    for (int p = 0; p < 4; p++)
        bAd[p] = bsU + ((lane & 15)*BST + wn*64 + p*16 + (lane >> 4)*8) * 2;

    auto issue = [&](int k0, int buf) {
        const unsigned ad = asU + buf * (ABUF*2);
        const unsigned bd = bsU + buf * (BBUF*2);
#pragma unroll
        for (int it = 0; it < 2; it++) {
            const int ch = tid*2 + it;                 // A: 512 chunks of 16B
            const int row = ch >> 2, c = (ch & 3)*8;
            cpa16(ad + (row*AST + c)*2, A + (size_t)(m0+row)*K + k0 + c);
            const int ch2 = tid + it*256;              // B: 512 chunks
            const int br = ch2 >> 4, bc = (ch2 & 15)*8;
            cpa16(bd + (br*BST + bc)*2, Bm + (size_t)(k0+br)*N + n0 + bc);
        }
        CP_COMMIT();
    };

    issue(0, 0);

    for (int k0 = 0; k0 < K; k0 += 32) {
        const int buf = (k0 >> 5) & 1;
        CP_WAIT0();
        __syncthreads();
        if (k0 + 32 < K) issue(k0 + 32, buf ^ 1);

        const unsigned aOff = buf * (ABUF*2);
        const unsigned bOff = buf * (BBUF*2);
#pragma unroll
        for (int ks = 0; ks < 2; ks++) {
            unsigned af[2][4];
            ldsm4(af[0], aAd[0] + aOff + ks*32);
            ldsm4(af[1], aAd[1] + aOff + ks*32);
#pragma unroll
            for (int p = 0; p < 4; p++) {
                unsigned bb[4];
                ldsm4t(bb, bAd[p] + bOff + ks*(16*BST*2));
#pragma unroll
                for (int mt = 0; mt < 2; mt++) {
                    mma16(acc[mt][2*p+0], af[mt], &bb[0]);
                    mma16(acc[mt][2*p+1], af[mt], &bb[2]);
                }
            }
        }
    }

    // epilogue
#pragma unroll
    for (int mt = 0; mt < 2; mt++) {
        const int r0 = m0 + wm*32 + mt*16 + (lane >> 2);
#pragma unroll
        for (int nt = 0; nt < 8; nt++) {
            const int c = n0 + wn*64 + nt*8 + (lane & 3)*2;
#pragma unroll
            for (int half = 0; half < 2; half++) {
                const int row = r0 + half*8;
                float vx = acc[mt][nt][half*2+0];
                float vy = acc[mt][nt][half*2+1];
                if (MODE == 0) {
                    float2 v; v.x = vx + bias[c]; v.y = vy + bias[c+1];
                    *(float2*)&C[(size_t)row*N + c] = v;
                } else {
                    const int b = row >> 11, n = row & 2047;
                    __half2 hv = __floats2half2_rn(vx, vy);
                    if (MODE == 1) {
                        const int h = c >> 6, d = c & 63;
                        *(__half2*)&g_Qh[((size_t)(b*H_+h)*N_ + n)*DH_ + d] = hv;
                    } else {
                        __half* base = (c >= 1024) ? g_Vh : g_Kh;
                        const int c2 = c & 1023;
                        const int h = c2 >> 6, d = c2 & 63;
                        *(__half2*)&base[((size_t)(b*H_+h)*N_ + n)*DH_ + d] = hv;
                    }
                }
            }
        }
    }
}

// ---------------------------------------------------------------------------
// RoPE in place (pair (d, d+32)); Q additionally pre-scaled by 1/8*log2(e).
// ---------------------------------------------------------------------------
__global__ void rope_kernel(const float* __restrict__ rot)
{
    const float QSC = 0.125f * 1.4426950408889634f;
    const int idx = blockIdx.x * blockDim.x + threadIdx.x;
    const int half = B_*H_*N_*32;
    if (idx >= 2*half) return;
    __half* buf = g_Qh;
    float scale = QSC;
    int t = idx;
    if (t >= half) { buf = g_Kh; t -= half; scale = 1.f; }
    const int d    = t & 31;
    const int rest = t >> 5;
    const int n    = rest & (N_-1);
    const size_t i1 = (size_t)rest * 64 + d;
    const size_t i2 = i1 + 32;
    const float p1 = rot[n*64 + d];
    const float p2 = rot[n*64 + d + 32];
    const float t1 = __half2float(buf[i1]);
    const float t2 = __half2float(buf[i2]);
    buf[i1] = __float2half_rn((t1*cosf(p1) - t2*sinf(p1)) * scale);
    buf[i2] = __float2half_rn((t2*cosf(p2) + t1*sinf(p2)) * scale);
}

// ---------------------------------------------------------------------------
// Flash attention (fp16 mma, register-resident P): 128-row blocks, 4 warps,
// 32 q-rows/warp, double-buffered cp.async K/V, exp2 softmax, alpha-skip.
// ---------------------------------------------------------------------------
#define KST 72
#define VST 72
#define KS_FL (64*KST)
#define VS_FL (64*VST)
#define ATT_BYTES ((2*KS_FL + 2*VS_FL)*2)     // 36864

__global__ __launch_bounds__(128)
void attn_mma()
{
    extern __shared__ __half smh[];
    __half* KsB = smh;                      // 2 bufs [64][72]
    __half* VsB = smh + 2*KS_FL;            // 2 bufs [64][72]

    const int tid  = threadIdx.x;
    const int lane = tid & 31;
    const int wid  = tid >> 5;
    const int bh = blockIdx.y;
    const int m0 = blockIdx.x * 128;

    const unsigned ksU = sptr(KsB);
    const unsigned vsU = sptr(VsB);

    // Q fragments: already scaled+rounded by rope; raw 4B loads
    const __half* Qb = g_Qh + (size_t)bh * N_ * DH_;
    const int qr = m0 + wid*32 + (lane >> 2);
    unsigned qf[2][4][4];
#pragma unroll
    for (int mt = 0; mt < 2; mt++) {
#pragma unroll
        for (int ks = 0; ks < 4; ks++) {
#pragma unroll
            for (int v = 0; v < 4; v++) {
                const int rr = qr + mt*16 + (v & 1)*8;
                const int cc = ks*16 + (lane & 3)*2 + (v >> 1)*8;
                qf[mt][ks][v] = *(const unsigned*)&Qb[(size_t)rr*64 + cc];
            }
        }
    }

    unsigned kAd[4], vAd[4];
#pragma unroll
    for (int p = 0; p < 4; p++)
        kAd[p] = ksU + ((p*16 + (lane & 7) + (lane >> 4)*8)*KST
                        + ((lane >> 3) & 1)*8) * 2;
#pragma unroll
    for (int dv = 0; dv < 4; dv++)
        vAd[dv] = vsU + ((lane & 15)*VST + dv*16 + (lane >> 4)*8) * 2;

    float mi[4] = {-1e30f, -1e30f, -1e30f, -1e30f};
    float li[4] = {0.f, 0.f, 0.f, 0.f};
    float o[2][8][4];
#pragma unroll
    for (int mt = 0; mt < 2; mt++)
#pragma unroll
        for (int nt = 0; nt < 8; nt++)
#pragma unroll
            for (int v = 0; v < 4; v++) o[mt][nt][v] = 0.f;

    const __half* KgB = g_Kh + (size_t)bh * N_ * DH_;
    const __half* VgB = g_Vh + (size_t)bh * N_ * DH_;

    auto issue = [&](int jt, int buf) {
        const __half* Kg = KgB + (size_t)jt * 64 * 64;
        const __half* Vg = VgB + (size_t)jt * 64 * 64;
        const unsigned kd = ksU + buf * (KS_FL*2);
        const unsigned vd = vsU + buf * (VS_FL*2);
#pragma unroll
        for (int it = 0; it < 4; it++) {
            const int t = tid + it*128;
            const int row = t >> 3, c8 = (t & 7) * 8;
            cpa16(kd + (row*KST + c8)*2, Kg + row*64 + c8);
            cpa16(vd + (row*VST + c8)*2, Vg + row*64 + c8);
        }
        CP_COMMIT();
    };

    issue(0, 0);

    for (int jt = 0; jt < N_/64; jt++) {
        const int buf = jt & 1;
        CP_WAIT0();
        __syncthreads();
        if (jt + 1 < N_/64) issue(jt + 1, buf ^ 1);

        const unsigned kOff = buf * (KS_FL*2);
        // --- S = Q' K^T ---
        float s[2][8][4];
#pragma unroll
        for (int mt = 0; mt < 2; mt++)
#pragma unroll
            for (int nt = 0; nt < 8; nt++)
#pragma unroll
                for (int v = 0; v < 4; v++) s[mt][nt][v] = 0.f;
#pragma unroll
        for (int ks = 0; ks < 4; ks++) {
#pragma unroll
            for (int p = 0; p < 4; p++) {
                unsigned bb[4];
                ldsm4(bb, kAd[p] + kOff + ks*32);
                mma16(s[0][2*p+0], qf[0][ks], &bb[0]);
                mma16(s[0][2*p+1], qf[0][ks], &bb[2]);
                mma16(s[1][2*p+0], qf[1][ks], &bb[0]);
                mma16(s[1][2*p+1], qf[1][ks], &bb[2]);
            }
        }

        // --- online softmax (base-2), P packed into register fragments ---
        unsigned ph[2][4][4];
#pragma unroll
        for (int mt = 0; mt < 2; mt++) {
            float mx0 = -1e30f, mx1 = -1e30f;
#pragma unroll
            for (int nt = 0; nt < 8; nt++) {
                mx0 = fmaxf(mx0, fmaxf(s[mt][nt][0], s[mt][nt][1]));
                mx1 = fmaxf(mx1, fmaxf(s[mt][nt][2], s[mt][nt][3]));
            }
#pragma unroll
            for (int off = 1; off <= 2; off <<= 1) {
                mx0 = fmaxf(mx0, __shfl_xor_sync(0xffffffffu, mx0, off));
                mx1 = fmaxf(mx1, __shfl_xor_sync(0xffffffffu, mx1, off));
            }
            const float mn0 = fmaxf(mi[mt*2+0], mx0);
            const float mn1 = fmaxf(mi[mt*2+1], mx1);
            const float al0 = exp2f(mi[mt*2+0] - mn0);
            const float al1 = exp2f(mi[mt*2+1] - mn1);
            float rs0 = 0.f, rs1 = 0.f;
#pragma unroll
            for (int nt = 0; nt < 8; nt++) {
                float p0 = exp2f(s[mt][nt][0] - mn0);
                float p1 = exp2f(s[mt][nt][1] - mn0);
                float p2 = exp2f(s[mt][nt][2] - mn1);
                float p3 = exp2f(s[mt][nt][3] - mn1);
                rs0 += p0 + p1; rs1 += p2 + p3;
                // pack: A-fragment of PV mma, k-chunk = nt>>1
                const int ks = nt >> 1, hi = (nt & 1) * 2;
                ph[mt][ks][hi+0] = h2u(__floats2half2_rn(p0, p1));
                ph[mt][ks][hi+1] = h2u(__floats2half2_rn(p2, p3));
            }
#pragma unroll
            for (int off = 1; off <= 2; off <<= 1) {
                rs0 += __shfl_xor_sync(0xffffffffu, rs0, off);
                rs1 += __shfl_xor_sync(0xffffffffu, rs1, off);
            }
            li[mt*2+0] = li[mt*2+0]*al0 + rs0;  mi[mt*2+0] = mn0;
            li[mt*2+1] = li[mt*2+1]*al1 + rs1;  mi[mt*2+1] = mn1;
            const bool skip = __all_sync(0xffffffffu,
                                         (al0 == 1.f) && (al1 == 1.f));
            if (!skip) {
#pragma unroll
                for (int nt = 0; nt < 8; nt++) {
                    o[mt][nt][0] *= al0; o[mt][nt][1] *= al0;
                    o[mt][nt][2] *= al1; o[mt][nt][3] *= al1;
                }
            }
        }

        // ph[mt][ks] is the row-major A fragment for k-chunk ks of P[16][64]:
        // [0]=h2(c0,c1) of s[2ks], [1]=h2(c2,c3) of s[2ks],
        // [2]=h2(c0,c1) of s[2ks+1], [3]=h2(c2,c3) of s[2ks+1].

        // --- O += P @ V ---
        const unsigned vOff = buf * (VS_FL*2);
#pragma unroll
        for (int ks = 0; ks < 4; ks++) {
#pragma unroll
            for (int dv = 0; dv < 4; dv++) {
                unsigned bb[4];
                ldsm4t(bb, vAd[dv] + vOff + ks*(16*VST*2));
                mma16(o[0][2*dv+0], ph[0][ks], &bb[0]);
                mma16(o[0][2*dv+1], ph[0][ks], &bb[2]);
                mma16(o[1][2*dv+0], ph[1][ks], &bb[0]);
                mma16(o[1][2*dv+1], ph[1][ks], &bb[2]);
            }
        }
    }

    // --- epilogue: normalize + fp16 write [b*n, h*64+d] ---
    const int b = bh >> 4, h = bh & 15;
#pragma unroll
    for (int mt = 0; mt < 2; mt++) {
        const float inv0 = 1.f / li[mt*2+0];
        const float inv1 = 1.f / li[mt*2+1];
        const int r0 = m0 + wid*32 + mt*16 + (lane >> 2);
#pragma unroll
        for (int nt = 0; nt < 8; nt++) {
            const int c = h*64 + nt*8 + (lane & 3)*2;
            *(__half2*)&g_Ah[((size_t)(b*N_ + r0))*D_ + c] =
                __floats2half2_rn(o[mt][nt][0]*inv0, o[mt][nt][1]*inv0);
            *(__half2*)&g_Ah[((size_t)(b*N_ + r0 + 8))*D_ + c] =
                __floats2half2_rn(o[mt][nt][2]*inv1, o[mt][nt][3]*inv1);
        }
    }
}

// ---------------------------------------------------------------------------
extern "C" void kernel_launch(void* const* d_in, const int* in_sizes, int n_in,
                              void* d_out, int out_size)
{
    const float* x    = (const float*)d_in[0];
    const float* rot  = (const float*)d_in[1];
    const float* Wq   = (const float*)d_in[2];
    const float* Wkv  = (const float*)d_in[3];
    const float* Wout = (const float*)d_in[4];
    const float* bout = (const float*)d_in[5];
    float* out = (float*)d_out;

    __half *gXh, *gWqh, *gWkvh, *gWoh, *gAh;
    cudaGetSymbolAddress((void**)&gXh,  g_Xh);
    cudaGetSymbolAddress((void**)&gWqh, g_Wqh);
    cudaGetSymbolAddress((void**)&gWkvh,g_Wkvh);
    cudaGetSymbolAddress((void**)&gWoh, g_Woh);
    cudaGetSymbolAddress((void**)&gAh,  g_Ah);
    cudaFuncSetAttribute(attn_mma,
                         cudaFuncAttributeMaxDynamicSharedMemorySize,
                         ATT_BYTES);

    cvt_h<<<2048, 256>>>((const float4*)x,    (uint2*)gXh,   MTOT*D_/4);
    cvt_h<<<1024, 256>>>((const float4*)Wq,   (uint2*)gWqh,  D_*D_/4);
    cvt_h<<<1024, 256>>>((const float4*)Wkv,  (uint2*)gWkvh, D_*2*D_/4);
    cvt_h<<<1024, 256>>>((const float4*)Wout, (uint2*)gWoh,  D_*D_/4);

    gemm_h<1><<<dim3(8, 64),  256>>>(gXh, gWqh,  nullptr, MTOT, 1024, 1024, nullptr);
    gemm_h<2><<<dim3(16, 64), 256>>>(gXh, gWkvh, nullptr, MTOT, 2048, 1024, nullptr);
    rope_kernel<<<(2*B_*H_*N_*32 + 255)/256, 256>>>(rot);
    attn_mma<<<dim3(N_/128, B_*H_), 128, ATT_BYTES>>>();
    gemm_h<0><<<dim3(8, 64),  256>>>(gAh, gWoh, out, MTOT, 1024, 1024, bout);
}

// round 11
// speedup vs baseline: 7.7469x; 1.0182x over previous
#include <cuda_runtime.h>
#include <cuda_fp16.h>
#include <math.h>

#define H_   16
#define DH_  64
#define B_   4
#define N_   2048
#define D_   1024
#define MTOT (B_*N_)     // 8192

__device__ __half g_Qh[(size_t)B_*H_*N_*DH_];   // [b,h,n,d]
__device__ __half g_Kh[(size_t)B_*H_*N_*DH_];
__device__ __half g_Vh[(size_t)B_*H_*N_*DH_];
__device__ __half g_Ah[(size_t)MTOT*D_];        // attention out, [b*n, h*d]
__device__ __half g_Xh[(size_t)MTOT*D_];        // x in fp16
__device__ __half g_Wqh[(size_t)D_*D_];
__device__ __half g_Wkvh[(size_t)D_*2*D_];
__device__ __half g_Woh[(size_t)D_*D_];
__device__ float  g_cos[(size_t)N_*DH_];
__device__ float  g_sin[(size_t)N_*DH_];

// ---------------------------------------------------------------------------
// helpers
// ---------------------------------------------------------------------------
__device__ __forceinline__ unsigned h2u(__half2 h) { return *(unsigned*)&h; }
__device__ __forceinline__ unsigned sptr(const void* p) {
    return (unsigned)__cvta_generic_to_shared(p);
}
__device__ __forceinline__ void mma16(float* c, const unsigned* a, const unsigned* b) {
    asm volatile("mma.sync.aligned.m16n8k16.row.col.f32.f16.f16.f32 "
                 "{%0,%1,%2,%3}, {%4,%5,%6,%7}, {%8,%9}, {%0,%1,%2,%3};"
                 : "+f"(c[0]), "+f"(c[1]), "+f"(c[2]), "+f"(c[3])
                 : "r"(a[0]), "r"(a[1]), "r"(a[2]), "r"(a[3]),
                   "r"(b[0]), "r"(b[1]));
}
__device__ __forceinline__ void ldsm4(unsigned* r, unsigned addr) {
    asm volatile("ldmatrix.sync.aligned.m8n8.x4.shared.b16 {%0,%1,%2,%3}, [%4];"
                 : "=r"(r[0]), "=r"(r[1]), "=r"(r[2]), "=r"(r[3]) : "r"(addr));
}
__device__ __forceinline__ void ldsm4t(unsigned* r, unsigned addr) {
    asm volatile("ldmatrix.sync.aligned.m8n8.x4.trans.shared.b16 {%0,%1,%2,%3}, [%4];"
                 : "=r"(r[0]), "=r"(r[1]), "=r"(r[2]), "=r"(r[3]) : "r"(addr));
}
__device__ __forceinline__ void cpa16(unsigned dst, const void* src) {
    asm volatile("cp.async.cg.shared.global [%0], [%1], 16;" :: "r"(dst), "l"(src));
}
#define CP_COMMIT() asm volatile("cp.async.commit_group;")
#define CP_WAIT0()  asm volatile("cp.async.wait_group 0;")
#define CP_WAIT1()  asm volatile("cp.async.wait_group 1;")

// ---------------------------------------------------------------------------
// f32 -> f16 conversion, unroll-4 for MLP
// ---------------------------------------------------------------------------
__global__ void cvt_h(const float4* __restrict__ src, uint2* __restrict__ dst, int n4)
{
    const int base = blockIdx.x * blockDim.x * 4 + threadIdx.x;
#pragma unroll
    for (int j = 0; j < 4; j++) {
        const int i = base + j * blockDim.x;
        if (i < n4) {
            float4 v = src[i];
            uint2 o;
            o.x = h2u(__floats2half2_rn(v.x, v.y));
            o.y = h2u(__floats2half2_rn(v.z, v.w));
            dst[i] = o;
        }
    }
}

// ---------------------------------------------------------------------------
// Precompute cos/sin tables of rot (131072 entries)
// ---------------------------------------------------------------------------
__global__ void prep_trig(const float* __restrict__ rot)
{
    const int i = blockIdx.x * blockDim.x + threadIdx.x;
    if (i < N_*DH_) {
        g_cos[i] = cosf(rot[i]);
        g_sin[i] = sinf(rot[i]);
    }
}

// ---------------------------------------------------------------------------
// FP16 GEMM (fp32 accum): 128x128 tile, BK=32, cp.async 3-stage ring.
// MODE 0: C = acc + bias (fp32); MODE 1: fp16 -> g_Qh; MODE 2: g_Kh/g_Vh
// ---------------------------------------------------------------------------
#define AST 40                       // 32 + 8 pad (halves)
#define BST 136                      // 128 + 8 pad (halves)
#define ABUF (128*AST)               // halves per A stage
#define BBUF (32*BST)                // halves per B stage
#define GEMM_BYTES ((3*ABUF + 3*BBUF)*2)   // 56832
template<int MODE>
__global__ __launch_bounds__(256)
void gemm_h(const __half* __restrict__ A, const __half* __restrict__ Bm,
            float* __restrict__ C, int M, int N, int K,
            const float* __restrict__ bias)
{
    extern __shared__ __half dsm[];
    __half* As = dsm;                 // 3 stages
    __half* Bs = dsm + 3*ABUF;
    const int tid  = threadIdx.x;
    const int lane = tid & 31;
    const int wid  = tid >> 5;
    const int wm   = wid & 3;
    const int wn   = wid >> 2;
    const int m0 = blockIdx.y * 128, n0 = blockIdx.x * 128;

    const unsigned asU = sptr(As);
    const unsigned bsU = sptr(Bs);

    float acc[2][8][4];
#pragma unroll
    for (int i = 0; i < 2; i++)
#pragma unroll
        for (int j = 0; j < 8; j++)
#pragma unroll
            for (int v = 0; v < 4; v++) acc[i][j][v] = 0.f;

    // fragment addresses (stage 0)
    unsigned aAd[2], bAd[4];
#pragma unroll
    for (int mt = 0; mt < 2; mt++)
        aAd[mt] = asU + ((wm*32 + mt*16 + (lane & 15))*AST + (lane >> 4)*8) * 2;
#pragma unroll
    for (int p = 0; p < 4; p++)
        bAd[p] = bsU + ((lane & 15)*BST + wn*64 + p*16 + (lane >> 4)*8) * 2;

    auto issue = [&](int k0, int s) {
        const unsigned ad = asU + s * (ABUF*2);
        const unsigned bd = bsU + s * (BBUF*2);
#pragma unroll
        for (int it = 0; it < 2; it++) {
            const int ch = tid*2 + it;                 // A: 512 chunks of 16B
            const int row = ch >> 2, c = (ch & 3)*8;
            cpa16(ad + (row*AST + c)*2, A + (size_t)(m0+row)*K + k0 + c);
            const int ch2 = tid + it*256;              // B: 512 chunks
            const int br = ch2 >> 4, bc = (ch2 & 15)*8;
            cpa16(bd + (br*BST + bc)*2, Bm + (size_t)(k0+br)*N + n0 + bc);
        }
        CP_COMMIT();
    };

    issue(0, 0);
    issue(32, 1);

    for (int k0 = 0; k0 < K; k0 += 32) {
        const int st = (k0 >> 5) % 3;
        if (k0 + 32 < K) { CP_WAIT1(); } else { CP_WAIT0(); }
        __syncthreads();
        if (k0 + 64 < K) issue(k0 + 64, ((k0 >> 5) + 2) % 3);

        const unsigned aOff = st * (ABUF*2);
        const unsigned bOff = st * (BBUF*2);
#pragma unroll
        for (int ks = 0; ks < 2; ks++) {
            unsigned af[2][4];
            ldsm4(af[0], aAd[0] + aOff + ks*32);
            ldsm4(af[1], aAd[1] + aOff + ks*32);
#pragma unroll
            for (int p = 0; p < 4; p++) {
                unsigned bb[4];
                ldsm4t(bb, bAd[p] + bOff + ks*(16*BST*2));
#pragma unroll
                for (int mt = 0; mt < 2; mt++) {
                    mma16(acc[mt][2*p+0], af[mt], &bb[0]);
                    mma16(acc[mt][2*p+1], af[mt], &bb[2]);
                }
            }
        }
    }

    // epilogue
#pragma unroll
    for (int mt = 0; mt < 2; mt++) {
        const int r0 = m0 + wm*32 + mt*16 + (lane >> 2);
#pragma unroll
        for (int nt = 0; nt < 8; nt++) {
            const int c = n0 + wn*64 + nt*8 + (lane & 3)*2;
#pragma unroll
            for (int half = 0; half < 2; half++) {
                const int row = r0 + half*8;
                float vx = acc[mt][nt][half*2+0];
                float vy = acc[mt][nt][half*2+1];
                if (MODE == 0) {
                    float2 v; v.x = vx + bias[c]; v.y = vy + bias[c+1];
                    *(float2*)&C[(size_t)row*N + c] = v;
                } else {
                    const int b = row >> 11, n = row & 2047;
                    __half2 hv = __floats2half2_rn(vx, vy);
                    if (MODE == 1) {
                        const int h = c >> 6, d = c & 63;
                        *(__half2*)&g_Qh[((size_t)(b*H_+h)*N_ + n)*DH_ + d] = hv;
                    } else {
                        __half* base = (c >= 1024) ? g_Vh : g_Kh;
                        const int c2 = c & 1023;
                        const int h = c2 >> 6, d = c2 & 63;
                        *(__half2*)&base[((size_t)(b*H_+h)*N_ + n)*DH_ + d] = hv;
                    }
                }
            }
        }
    }
}

// ---------------------------------------------------------------------------
// RoPE via precomputed tables, half2-vectorized; Q pre-scaled by 1/8*log2(e).
// Thread handles (d2,d2+1) and partners (d2+32,d2+33).
// ---------------------------------------------------------------------------
__global__ void rope_kernel()
{
    const float QSC = 0.125f * 1.4426950408889634f;
    const int idx = blockIdx.x * blockDim.x + threadIdx.x;
    const int half = B_*H_*N_*16;
    if (idx >= 2*half) return;
    __half* buf = g_Qh;
    float sc = QSC;
    int t = idx;
    if (t >= half) { buf = g_Kh; t -= half; sc = 1.f; }
    const int d2   = (t & 15) * 2;
    const int rest = t >> 4;
    const int n    = rest & (N_-1);
    const size_t base = (size_t)rest * 64;
    float2 f1 = __half22float2(*(__half2*)&buf[base + d2]);
    float2 f2 = __half22float2(*(__half2*)&buf[base + d2 + 32]);
    const float2 c1 = *(const float2*)&g_cos[n*64 + d2];
    const float2 s1 = *(const float2*)&g_sin[n*64 + d2];
    const float2 c2 = *(const float2*)&g_cos[n*64 + d2 + 32];
    const float2 s2 = *(const float2*)&g_sin[n*64 + d2 + 32];
    float2 o1, o2;
    o1.x = (f1.x*c1.x - f2.x*s1.x) * sc;
    o1.y = (f1.y*c1.y - f2.y*s1.y) * sc;
    o2.x = (f2.x*c2.x + f1.x*s2.x) * sc;
    o2.y = (f2.y*c2.y + f1.y*s2.y) * sc;
    *(__half2*)&buf[base + d2]      = __floats2half2_rn(o1.x, o1.y);
    *(__half2*)&buf[base + d2 + 32] = __floats2half2_rn(o2.x, o2.y);
}

// ---------------------------------------------------------------------------
// Flash attention (fp16 mma, register-resident P): 128-row blocks, 4 warps,
// 32 q-rows/warp, 3-stage cp.async K/V ring, exp2 softmax, alpha-skip.
// ---------------------------------------------------------------------------
#define KST 72
#define VST 72
#define KS_FL (64*KST)
#define VS_FL (64*VST)
#define ATT_BYTES ((3*KS_FL + 3*VS_FL)*2)     // 55296
#define NT_ (N_/64)

__global__ __launch_bounds__(128)
void attn_mma()
{
    extern __shared__ __half smh[];
    __half* KsB = smh;                      // 3 bufs [64][72]
    __half* VsB = smh + 3*KS_FL;            // 3 bufs [64][72]

    const int tid  = threadIdx.x;
    const int lane = tid & 31;
    const int wid  = tid >> 5;
    const int bh = blockIdx.y;
    const int m0 = blockIdx.x * 128;

    const unsigned ksU = sptr(KsB);
    const unsigned vsU = sptr(VsB);

    // Q fragments: already scaled+rounded by rope; raw 4B loads
    const __half* Qb = g_Qh + (size_t)bh * N_ * DH_;
    const int qr = m0 + wid*32 + (lane >> 2);
    unsigned qf[2][4][4];
#pragma unroll
    for (int mt = 0; mt < 2; mt++) {
#pragma unroll
        for (int ks = 0; ks < 4; ks++) {
#pragma unroll
            for (int v = 0; v < 4; v++) {
                const int rr = qr + mt*16 + (v & 1)*8;
                const int cc = ks*16 + (lane & 3)*2 + (v >> 1)*8;
                qf[mt][ks][v] = *(const unsigned*)&Qb[(size_t)rr*64 + cc];
            }
        }
    }

    unsigned kAd[4], vAd[4];
#pragma unroll
    for (int p = 0; p < 4; p++)
        kAd[p] = ksU + ((p*16 + (lane & 7) + (lane >> 4)*8)*KST
                        + ((lane >> 3) & 1)*8) * 2;
#pragma unroll
    for (int dv = 0; dv < 4; dv++)
        vAd[dv] = vsU + ((lane & 15)*VST + dv*16 + (lane >> 4)*8) * 2;

    float mi[4] = {-1e30f, -1e30f, -1e30f, -1e30f};
    float li[4] = {0.f, 0.f, 0.f, 0.f};
    float o[2][8][4];
#pragma unroll
    for (int mt = 0; mt < 2; mt++)
#pragma unroll
        for (int nt = 0; nt < 8; nt++)
#pragma unroll
            for (int v = 0; v < 4; v++) o[mt][nt][v] = 0.f;

    const __half* KgB = g_Kh + (size_t)bh * N_ * DH_;
    const __half* VgB = g_Vh + (size_t)bh * N_ * DH_;

    auto issue = [&](int jt, int s) {
        const __half* Kg = KgB + (size_t)jt * 64 * 64;
        const __half* Vg = VgB + (size_t)jt * 64 * 64;
        const unsigned kd = ksU + s * (KS_FL*2);
        const unsigned vd = vsU + s * (VS_FL*2);
#pragma unroll
        for (int it = 0; it < 4; it++) {
            const int t = tid + it*128;
            const int row = t >> 3, c8 = (t & 7) * 8;
            cpa16(kd + (row*KST + c8)*2, Kg + row*64 + c8);
            cpa16(vd + (row*VST + c8)*2, Vg + row*64 + c8);
        }
        CP_COMMIT();
    };

    issue(0, 0);
    issue(1, 1);

    for (int jt = 0; jt < NT_; jt++) {
        const int st = jt % 3;
        if (jt + 1 < NT_) { CP_WAIT1(); } else { CP_WAIT0(); }
        __syncthreads();
        if (jt + 2 < NT_) issue(jt + 2, (jt + 2) % 3);

        const unsigned kOff = st * (KS_FL*2);
        // --- S = Q' K^T ---
        float s[2][8][4];
#pragma unroll
        for (int mt = 0; mt < 2; mt++)
#pragma unroll
            for (int nt = 0; nt < 8; nt++)
#pragma unroll
                for (int v = 0; v < 4; v++) s[mt][nt][v] = 0.f;
#pragma unroll
        for (int ks = 0; ks < 4; ks++) {
#pragma unroll
            for (int p = 0; p < 4; p++) {
                unsigned bb[4];
                ldsm4(bb, kAd[p] + kOff + ks*32);
                mma16(s[0][2*p+0], qf[0][ks], &bb[0]);
                mma16(s[0][2*p+1], qf[0][ks], &bb[2]);
                mma16(s[1][2*p+0], qf[1][ks], &bb[0]);
                mma16(s[1][2*p+1], qf[1][ks], &bb[2]);
            }
        }

        // --- online softmax (base-2), P packed into register fragments ---
        unsigned ph[2][4][4];
#pragma unroll
        for (int mt = 0; mt < 2; mt++) {
            float mx0 = -1e30f, mx1 = -1e30f;
#pragma unroll
            for (int nt = 0; nt < 8; nt++) {
                mx0 = fmaxf(mx0, fmaxf(s[mt][nt][0], s[mt][nt][1]));
                mx1 = fmaxf(mx1, fmaxf(s[mt][nt][2], s[mt][nt][3]));
            }
#pragma unroll
            for (int off = 1; off <= 2; off <<= 1) {
                mx0 = fmaxf(mx0, __shfl_xor_sync(0xffffffffu, mx0, off));
                mx1 = fmaxf(mx1, __shfl_xor_sync(0xffffffffu, mx1, off));
            }
            const float mn0 = fmaxf(mi[mt*2+0], mx0);
            const float mn1 = fmaxf(mi[mt*2+1], mx1);
            const float al0 = exp2f(mi[mt*2+0] - mn0);
            const float al1 = exp2f(mi[mt*2+1] - mn1);
            float rs0 = 0.f, rs1 = 0.f;
#pragma unroll
            for (int nt = 0; nt < 8; nt++) {
                float p0 = exp2f(s[mt][nt][0] - mn0);
                float p1 = exp2f(s[mt][nt][1] - mn0);
                float p2 = exp2f(s[mt][nt][2] - mn1);
                float p3 = exp2f(s[mt][nt][3] - mn1);
                rs0 += p0 + p1; rs1 += p2 + p3;
                const int ks = nt >> 1, hi = (nt & 1) * 2;
                ph[mt][ks][hi+0] = h2u(__floats2half2_rn(p0, p1));
                ph[mt][ks][hi+1] = h2u(__floats2half2_rn(p2, p3));
            }
#pragma unroll
            for (int off = 1; off <= 2; off <<= 1) {
                rs0 += __shfl_xor_sync(0xffffffffu, rs0, off);
                rs1 += __shfl_xor_sync(0xffffffffu, rs1, off);
            }
            li[mt*2+0] = li[mt*2+0]*al0 + rs0;  mi[mt*2+0] = mn0;
            li[mt*2+1] = li[mt*2+1]*al1 + rs1;  mi[mt*2+1] = mn1;
            const bool skip = __all_sync(0xffffffffu,
                                         (al0 == 1.f) && (al1 == 1.f));
            if (!skip) {
#pragma unroll
                for (int nt = 0; nt < 8; nt++) {
                    o[mt][nt][0] *= al0; o[mt][nt][1] *= al0;
                    o[mt][nt][2] *= al1; o[mt][nt][3] *= al1;
                }
            }
        }

        // --- O += P @ V ---
        const unsigned vOff = st * (VS_FL*2);
#pragma unroll
        for (int ks = 0; ks < 4; ks++) {
#pragma unroll
            for (int dv = 0; dv < 4; dv++) {
                unsigned bb[4];
                ldsm4t(bb, vAd[dv] + vOff + ks*(16*VST*2));
                mma16(o[0][2*dv+0], ph[0][ks], &bb[0]);
                mma16(o[0][2*dv+1], ph[0][ks], &bb[2]);
                mma16(o[1][2*dv+0], ph[1][ks], &bb[0]);
                mma16(o[1][2*dv+1], ph[1][ks], &bb[2]);
            }
        }
    }

    // --- epilogue: normalize + fp16 write [b*n, h*64+d] ---
    const int b = bh >> 4, h = bh & 15;
#pragma unroll
    for (int mt = 0; mt < 2; mt++) {
        const float inv0 = 1.f / li[mt*2+0];
        const float inv1 = 1.f / li[mt*2+1];
        const int r0 = m0 + wid*32 + mt*16 + (lane >> 2);
#pragma unroll
        for (int nt = 0; nt < 8; nt++) {
            const int c = h*64 + nt*8 + (lane & 3)*2;
            *(__half2*)&g_Ah[((size_t)(b*N_ + r0))*D_ + c] =
                __floats2half2_rn(o[mt][nt][0]*inv0, o[mt][nt][1]*inv0);
            *(__half2*)&g_Ah[((size_t)(b*N_ + r0 + 8))*D_ + c] =
                __floats2half2_rn(o[mt][nt][2]*inv1, o[mt][nt][3]*inv1);
        }
    }
}

// ---------------------------------------------------------------------------
extern "C" void kernel_launch(void* const* d_in, const int* in_sizes, int n_in,
                              void* d_out, int out_size)
{
    const float* x    = (const float*)d_in[0];
    const float* rot  = (const float*)d_in[1];
    const float* Wq   = (const float*)d_in[2];
    const float* Wkv  = (const float*)d_in[3];
    const float* Wout = (const float*)d_in[4];
    const float* bout = (const float*)d_in[5];
    float* out = (float*)d_out;

    __half *gXh, *gWqh, *gWkvh, *gWoh, *gAh;
    cudaGetSymbolAddress((void**)&gXh,  g_Xh);
    cudaGetSymbolAddress((void**)&gWqh, g_Wqh);
    cudaGetSymbolAddress((void**)&gWkvh,g_Wkvh);
    cudaGetSymbolAddress((void**)&gWoh, g_Woh);
    cudaGetSymbolAddress((void**)&gAh,  g_Ah);

    cudaFuncSetAttribute(attn_mma,
                         cudaFuncAttributeMaxDynamicSharedMemorySize, ATT_BYTES);
    cudaFuncSetAttribute(gemm_h<0>,
                         cudaFuncAttributeMaxDynamicSharedMemorySize, GEMM_BYTES);
    cudaFuncSetAttribute(gemm_h<1>,
                         cudaFuncAttributeMaxDynamicSharedMemorySize, GEMM_BYTES);
    cudaFuncSetAttribute(gemm_h<2>,
                         cudaFuncAttributeMaxDynamicSharedMemorySize, GEMM_BYTES);

    prep_trig<<<(N_*DH_ + 255)/256, 256>>>(rot);
    cvt_h<<<MTOT*D_/4/1024, 256>>>((const float4*)x,    (uint2*)gXh,   MTOT*D_/4);
    cvt_h<<<D_*D_/4/1024,   256>>>((const float4*)Wq,   (uint2*)gWqh,  D_*D_/4);
    cvt_h<<<D_*2*D_/4/1024, 256>>>((const float4*)Wkv,  (uint2*)gWkvh, D_*2*D_/4);
    cvt_h<<<D_*D_/4/1024,   256>>>((const float4*)Wout, (uint2*)gWoh,  D_*D_/4);

    gemm_h<1><<<dim3(8, 64),  256, GEMM_BYTES>>>(gXh, gWqh,  nullptr, MTOT, 1024, 1024, nullptr);
    gemm_h<2><<<dim3(16, 64), 256, GEMM_BYTES>>>(gXh, gWkvh, nullptr, MTOT, 2048, 1024, nullptr);
    rope_kernel<<<(2*B_*H_*N_*16 + 255)/256, 256>>>();
    attn_mma<<<dim3(N_/128, B_*H_), 128, ATT_BYTES>>>();
    gemm_h<0><<<dim3(8, 64),  256, GEMM_BYTES>>>(gAh, gWoh, out, MTOT, 1024, 1024, bout);
}

// round 12
// speedup vs baseline: 7.8514x; 1.0135x over previous
#include <cuda_runtime.h>
#include <cuda_fp16.h>
#include <math.h>

#define H_   16
#define DH_  64
#define B_   4
#define N_   2048
#define D_   1024
#define MTOT (B_*N_)     // 8192

__device__ __half g_Qh[(size_t)B_*H_*N_*DH_];   // [b,h,n,d]
__device__ __half g_Kh[(size_t)B_*H_*N_*DH_];
__device__ __half g_Vh[(size_t)B_*H_*N_*DH_];
__device__ __half g_Ah[(size_t)MTOT*D_];        // attention out, [b*n, h*d]
__device__ __half g_Xh[(size_t)MTOT*D_];        // x in fp16
__device__ __half g_Wqh[(size_t)D_*D_];
__device__ __half g_Wkvh[(size_t)D_*2*D_];
__device__ __half g_Woh[(size_t)D_*D_];
__device__ float  g_cos[(size_t)N_*DH_];
__device__ float  g_sin[(size_t)N_*DH_];

// ---------------------------------------------------------------------------
// helpers
// ---------------------------------------------------------------------------
__device__ __forceinline__ unsigned h2u(__half2 h) { return *(unsigned*)&h; }
__device__ __forceinline__ unsigned sptr(const void* p) {
    return (unsigned)__cvta_generic_to_shared(p);
}
__device__ __forceinline__ void mma16(float* c, const unsigned* a, const unsigned* b) {
    asm volatile("mma.sync.aligned.m16n8k16.row.col.f32.f16.f16.f32 "
                 "{%0,%1,%2,%3}, {%4,%5,%6,%7}, {%8,%9}, {%0,%1,%2,%3};"
                 : "+f"(c[0]), "+f"(c[1]), "+f"(c[2]), "+f"(c[3])
                 : "r"(a[0]), "r"(a[1]), "r"(a[2]), "r"(a[3]),
                   "r"(b[0]), "r"(b[1]));
}
__device__ __forceinline__ void ldsm4(unsigned* r, unsigned addr) {
    asm volatile("ldmatrix.sync.aligned.m8n8.x4.shared.b16 {%0,%1,%2,%3}, [%4];"
                 : "=r"(r[0]), "=r"(r[1]), "=r"(r[2]), "=r"(r[3]) : "r"(addr));
}
__device__ __forceinline__ void ldsm4t(unsigned* r, unsigned addr) {
    asm volatile("ldmatrix.sync.aligned.m8n8.x4.trans.shared.b16 {%0,%1,%2,%3}, [%4];"
                 : "=r"(r[0]), "=r"(r[1]), "=r"(r[2]), "=r"(r[3]) : "r"(addr));
}
__device__ __forceinline__ void cpa16(unsigned dst, const void* src) {
    asm volatile("cp.async.cg.shared.global [%0], [%1], 16;" :: "r"(dst), "l"(src));
}
#define CP_COMMIT() asm volatile("cp.async.commit_group;")
#define CP_WAIT0()  asm volatile("cp.async.wait_group 0;")
#define CP_WAIT1()  asm volatile("cp.async.wait_group 1;")

// ---------------------------------------------------------------------------
// f32 -> f16 conversion, unroll-4 for MLP
// ---------------------------------------------------------------------------
__global__ void cvt_h(const float4* __restrict__ src, uint2* __restrict__ dst, int n4)
{
    const int base = blockIdx.x * blockDim.x * 4 + threadIdx.x;
#pragma unroll
    for (int j = 0; j < 4; j++) {
        const int i = base + j * blockDim.x;
        if (i < n4) {
            float4 v = src[i];
            uint2 o;
            o.x = h2u(__floats2half2_rn(v.x, v.y));
            o.y = h2u(__floats2half2_rn(v.z, v.w));
            dst[i] = o;
        }
    }
}

// ---------------------------------------------------------------------------
// Precompute cos/sin tables of rot
// ---------------------------------------------------------------------------
__global__ void prep_trig(const float* __restrict__ rot)
{
    const int i = blockIdx.x * blockDim.x + threadIdx.x;
    if (i < N_*DH_) {
        g_cos[i] = cosf(rot[i]);
        g_sin[i] = sinf(rot[i]);
    }
}

// ---------------------------------------------------------------------------
// Shared GEMM plumbing: 128x128 tile, BK=32, 3-stage cp.async ring.
// ---------------------------------------------------------------------------
#define AST 40                       // 32 + 8 pad (halves)
#define BST 136                      // 128 + 8 pad (halves)
#define ABUF (128*AST)
#define BBUF (32*BST)
#define GEMM_BYTES ((3*ABUF + 3*BBUF)*2)   // 56832

// ---------------------------------------------------------------------------
// Fused QKV projection GEMM: N' = 3072 (Q | K | V), rope+scale in epilogue.
// ---------------------------------------------------------------------------
__global__ __launch_bounds__(256)
void gemm_qkv(const __half* __restrict__ A,
              const __half* __restrict__ Wq, const __half* __restrict__ Wkv)
{
    extern __shared__ __half dsm[];
    __half* As = dsm;
    __half* Bs = dsm + 3*ABUF;
    const int tid  = threadIdx.x;
    const int lane = tid & 31;
    const int wid  = tid >> 5;
    const int wm   = wid & 3;
    const int wn   = wid >> 2;
    const int m0 = blockIdx.y * 128, n0 = blockIdx.x * 128;
    const int K = D_;

    // B source for this block's 128 columns
    const __half* Bp; int ldb;
    if (n0 < 1024) { Bp = Wq  + n0;          ldb = 1024; }
    else           { Bp = Wkv + (n0 - 1024); ldb = 2048; }

    const unsigned asU = sptr(As);
    const unsigned bsU = sptr(Bs);

    float acc[2][8][4];
#pragma unroll
    for (int i = 0; i < 2; i++)
#pragma unroll
        for (int j = 0; j < 8; j++)
#pragma unroll
            for (int v = 0; v < 4; v++) acc[i][j][v] = 0.f;

    unsigned aAd[2], bAd[4];
#pragma unroll
    for (int mt = 0; mt < 2; mt++)
        aAd[mt] = asU + ((wm*32 + mt*16 + (lane & 15))*AST + (lane >> 4)*8) * 2;
#pragma unroll
    for (int p = 0; p < 4; p++)
        bAd[p] = bsU + ((lane & 15)*BST + wn*64 + p*16 + (lane >> 4)*8) * 2;

    auto issue = [&](int k0, int s) {
        const unsigned ad = asU + s * (ABUF*2);
        const unsigned bd = bsU + s * (BBUF*2);
#pragma unroll
        for (int it = 0; it < 2; it++) {
            const int ch = tid*2 + it;
            const int row = ch >> 2, c = (ch & 3)*8;
            cpa16(ad + (row*AST + c)*2, A + (size_t)(m0+row)*K + k0 + c);
            const int ch2 = tid + it*256;
            const int br = ch2 >> 4, bc = (ch2 & 15)*8;
            cpa16(bd + (br*BST + bc)*2, Bp + (size_t)(k0+br)*ldb + bc);
        }
        CP_COMMIT();
    };

    issue(0, 0);
    issue(32, 1);

    for (int k0 = 0; k0 < K; k0 += 32) {
        const int st = (k0 >> 5) % 3;
        if (k0 + 32 < K) { CP_WAIT1(); } else { CP_WAIT0(); }
        __syncthreads();
        if (k0 + 64 < K) issue(k0 + 64, ((k0 >> 5) + 2) % 3);

        const unsigned aOff = st * (ABUF*2);
        const unsigned bOff = st * (BBUF*2);
#pragma unroll
        for (int ks = 0; ks < 2; ks++) {
            unsigned af[2][4];
            ldsm4(af[0], aAd[0] + aOff + ks*32);
            ldsm4(af[1], aAd[1] + aOff + ks*32);
#pragma unroll
            for (int p = 0; p < 4; p++) {
                unsigned bb[4];
                ldsm4t(bb, bAd[p] + bOff + ks*(16*BST*2));
#pragma unroll
                for (int mt = 0; mt < 2; mt++) {
                    mma16(acc[mt][2*p+0], af[mt], &bb[0]);
                    mma16(acc[mt][2*p+1], af[mt], &bb[2]);
                }
            }
        }
    }

    // --- epilogue with fused rope (+ QSC on Q) ---
    const float QSC = 0.125f * 1.4426950408889634f;
    const int cbase = n0 + wn*64;          // one head-wide group
    const int region = cbase >> 10;        // 0=Q, 1=K, 2=V
    const int h = (cbase >> 6) & 15;
    __half* dst = (region == 0) ? g_Qh : (region == 1) ? g_Kh : g_Vh;

#pragma unroll
    for (int mt = 0; mt < 2; mt++) {
        const int r0 = m0 + wm*32 + mt*16 + (lane >> 2);
#pragma unroll
        for (int half = 0; half < 2; half++) {
            const int row = r0 + half*8;
            const int b = row >> 11, n = row & 2047;
            __half* rowp = dst + ((size_t)(b*H_ + h)*N_ + n)*DH_;
#pragma unroll
            for (int nt = 0; nt < 4; nt++) {
                const int d = nt*8 + (lane & 3)*2;      // d < 32
                float x1 = acc[mt][nt  ][half*2+0];
                float y1 = acc[mt][nt  ][half*2+1];
                float x2 = acc[mt][nt+4][half*2+0];
                float y2 = acc[mt][nt+4][half*2+1];
                if (region < 2) {
                    const float2 c1 = *(const float2*)&g_cos[n*64 + d];
                    const float2 s1 = *(const float2*)&g_sin[n*64 + d];
                    const float2 c2 = *(const float2*)&g_cos[n*64 + d + 32];
                    const float2 s2 = *(const float2*)&g_sin[n*64 + d + 32];
                    float o1x = x1*c1.x - x2*s1.x;
                    float o1y = y1*c1.y - y2*s1.y;
                    float o2x = x2*c2.x + x1*s2.x;
                    float o2y = y2*c2.y + y1*s2.y;
                    if (region == 0) {
                        o1x *= QSC; o1y *= QSC; o2x *= QSC; o2y *= QSC;
                    }
                    x1 = o1x; y1 = o1y; x2 = o2x; y2 = o2y;
                }
                *(__half2*)&rowp[d]      = __floats2half2_rn(x1, y1);
                *(__half2*)&rowp[d + 32] = __floats2half2_rn(x2, y2);
            }
        }
    }
}

// ---------------------------------------------------------------------------
// Output GEMM: out = g_Ah @ Woh + bias  (fp32 out)
// ---------------------------------------------------------------------------
__global__ __launch_bounds__(256)
void gemm_out(const __half* __restrict__ A, const __half* __restrict__ Bm,
              float* __restrict__ C, const float* __restrict__ bias)
{
    extern __shared__ __half dsm[];
    __half* As = dsm;
    __half* Bs = dsm + 3*ABUF;
    const int tid  = threadIdx.x;
    const int lane = tid & 31;
    const int wid  = tid >> 5;
    const int wm   = wid & 3;
    const int wn   = wid >> 2;
    const int m0 = blockIdx.y * 128, n0 = blockIdx.x * 128;
    const int K = D_, N = D_;

    const unsigned asU = sptr(As);
    const unsigned bsU = sptr(Bs);

    float acc[2][8][4];
#pragma unroll
    for (int i = 0; i < 2; i++)
#pragma unroll
        for (int j = 0; j < 8; j++)
#pragma unroll
            for (int v = 0; v < 4; v++) acc[i][j][v] = 0.f;

    unsigned aAd[2], bAd[4];
#pragma unroll
    for (int mt = 0; mt < 2; mt++)
        aAd[mt] = asU + ((wm*32 + mt*16 + (lane & 15))*AST + (lane >> 4)*8) * 2;
#pragma unroll
    for (int p = 0; p < 4; p++)
        bAd[p] = bsU + ((lane & 15)*BST + wn*64 + p*16 + (lane >> 4)*8) * 2;

    auto issue = [&](int k0, int s) {
        const unsigned ad = asU + s * (ABUF*2);
        const unsigned bd = bsU + s * (BBUF*2);
#pragma unroll
        for (int it = 0; it < 2; it++) {
            const int ch = tid*2 + it;
            const int row = ch >> 2, c = (ch & 3)*8;
            cpa16(ad + (row*AST + c)*2, A + (size_t)(m0+row)*K + k0 + c);
            const int ch2 = tid + it*256;
            const int br = ch2 >> 4, bc = (ch2 & 15)*8;
            cpa16(bd + (br*BST + bc)*2, Bm + (size_t)(k0+br)*N + n0 + bc);
        }
        CP_COMMIT();
    };

    issue(0, 0);
    issue(32, 1);

    for (int k0 = 0; k0 < K; k0 += 32) {
        const int st = (k0 >> 5) % 3;
        if (k0 + 32 < K) { CP_WAIT1(); } else { CP_WAIT0(); }
        __syncthreads();
        if (k0 + 64 < K) issue(k0 + 64, ((k0 >> 5) + 2) % 3);

        const unsigned aOff = st * (ABUF*2);
        const unsigned bOff = st * (BBUF*2);
#pragma unroll
        for (int ks = 0; ks < 2; ks++) {
            unsigned af[2][4];
            ldsm4(af[0], aAd[0] + aOff + ks*32);
            ldsm4(af[1], aAd[1] + aOff + ks*32);
#pragma unroll
            for (int p = 0; p < 4; p++) {
                unsigned bb[4];
                ldsm4t(bb, bAd[p] + bOff + ks*(16*BST*2));
#pragma unroll
                for (int mt = 0; mt < 2; mt++) {
                    mma16(acc[mt][2*p+0], af[mt], &bb[0]);
                    mma16(acc[mt][2*p+1], af[mt], &bb[2]);
                }
            }
        }
    }

#pragma unroll
    for (int mt = 0; mt < 2; mt++) {
        const int r0 = m0 + wm*32 + mt*16 + (lane >> 2);
#pragma unroll
        for (int nt = 0; nt < 8; nt++) {
            const int c = n0 + wn*64 + nt*8 + (lane & 3)*2;
#pragma unroll
            for (int half = 0; half < 2; half++) {
                const int row = r0 + half*8;
                float2 v;
                v.x = acc[mt][nt][half*2+0] + bias[c];
                v.y = acc[mt][nt][half*2+1] + bias[c+1];
                *(float2*)&C[(size_t)row*N + c] = v;
            }
        }
    }
}

// ---------------------------------------------------------------------------
// Flash attention (fp16 mma, register-resident P): 128-row blocks, 4 warps,
// 32 q-rows/warp, 3-stage cp.async K/V ring, exp2 softmax, alpha-skip.
// ---------------------------------------------------------------------------
#define KST 72
#define VST 72
#define KS_FL (64*KST)
#define VS_FL (64*VST)
#define ATT_BYTES ((3*KS_FL + 3*VS_FL)*2)     // 55296
#define NT_ (N_/64)

__global__ __launch_bounds__(128)
void attn_mma()
{
    extern __shared__ __half smh[];
    __half* KsB = smh;
    __half* VsB = smh + 3*KS_FL;

    const int tid  = threadIdx.x;
    const int lane = tid & 31;
    const int wid  = tid >> 5;
    const int bh = blockIdx.y;
    const int m0 = blockIdx.x * 128;

    const unsigned ksU = sptr(KsB);
    const unsigned vsU = sptr(VsB);

    const __half* Qb = g_Qh + (size_t)bh * N_ * DH_;
    const int qr = m0 + wid*32 + (lane >> 2);
    unsigned qf[2][4][4];
#pragma unroll
    for (int mt = 0; mt < 2; mt++) {
#pragma unroll
        for (int ks = 0; ks < 4; ks++) {
#pragma unroll
            for (int v = 0; v < 4; v++) {
                const int rr = qr + mt*16 + (v & 1)*8;
                const int cc = ks*16 + (lane & 3)*2 + (v >> 1)*8;
                qf[mt][ks][v] = *(const unsigned*)&Qb[(size_t)rr*64 + cc];
            }
        }
    }

    unsigned kAd[4], vAd[4];
#pragma unroll
    for (int p = 0; p < 4; p++)
        kAd[p] = ksU + ((p*16 + (lane & 7) + (lane >> 4)*8)*KST
                        + ((lane >> 3) & 1)*8) * 2;
#pragma unroll
    for (int dv = 0; dv < 4; dv++)
        vAd[dv] = vsU + ((lane & 15)*VST + dv*16 + (lane >> 4)*8) * 2;

    float mi[4] = {-1e30f, -1e30f, -1e30f, -1e30f};
    float li[4] = {0.f, 0.f, 0.f, 0.f};
    float o[2][8][4];
#pragma unroll
    for (int mt = 0; mt < 2; mt++)
#pragma unroll
        for (int nt = 0; nt < 8; nt++)
#pragma unroll
            for (int v = 0; v < 4; v++) o[mt][nt][v] = 0.f;

    const __half* KgB = g_Kh + (size_t)bh * N_ * DH_;
    const __half* VgB = g_Vh + (size_t)bh * N_ * DH_;

    auto issue = [&](int jt, int s) {
        const __half* Kg = KgB + (size_t)jt * 64 * 64;
        const __half* Vg = VgB + (size_t)jt * 64 * 64;
        const unsigned kd = ksU + s * (KS_FL*2);
        const unsigned vd = vsU + s * (VS_FL*2);
#pragma unroll
        for (int it = 0; it < 4; it++) {
            const int t = tid + it*128;
            const int row = t >> 3, c8 = (t & 7) * 8;
            cpa16(kd + (row*KST + c8)*2, Kg + row*64 + c8);
            cpa16(vd + (row*VST + c8)*2, Vg + row*64 + c8);
        }
        CP_COMMIT();
    };

    issue(0, 0);
    issue(1, 1);

    for (int jt = 0; jt < NT_; jt++) {
        const int st = jt % 3;
        if (jt + 1 < NT_) { CP_WAIT1(); } else { CP_WAIT0(); }
        __syncthreads();
        if (jt + 2 < NT_) issue(jt + 2, (jt + 2) % 3);

        const unsigned kOff = st * (KS_FL*2);
        float s[2][8][4];
#pragma unroll
        for (int mt = 0; mt < 2; mt++)
#pragma unroll
            for (int nt = 0; nt < 8; nt++)
#pragma unroll
                for (int v = 0; v < 4; v++) s[mt][nt][v] = 0.f;
#pragma unroll
        for (int ks = 0; ks < 4; ks++) {
#pragma unroll
            for (int p = 0; p < 4; p++) {
                unsigned bb[4];
                ldsm4(bb, kAd[p] + kOff + ks*32);
                mma16(s[0][2*p+0], qf[0][ks], &bb[0]);
                mma16(s[0][2*p+1], qf[0][ks], &bb[2]);
                mma16(s[1][2*p+0], qf[1][ks], &bb[0]);
                mma16(s[1][2*p+1], qf[1][ks], &bb[2]);
            }
        }

        unsigned ph[2][4][4];
#pragma unroll
        for (int mt = 0; mt < 2; mt++) {
            float mx0 = -1e30f, mx1 = -1e30f;
#pragma unroll
            for (int nt = 0; nt < 8; nt++) {
                mx0 = fmaxf(mx0, fmaxf(s[mt][nt][0], s[mt][nt][1]));
                mx1 = fmaxf(mx1, fmaxf(s[mt][nt][2], s[mt][nt][3]));
            }
#pragma unroll
            for (int off = 1; off <= 2; off <<= 1) {
                mx0 = fmaxf(mx0, __shfl_xor_sync(0xffffffffu, mx0, off));
                mx1 = fmaxf(mx1, __shfl_xor_sync(0xffffffffu, mx1, off));
            }
            const float mn0 = fmaxf(mi[mt*2+0], mx0);
            const float mn1 = fmaxf(mi[mt*2+1], mx1);
            const float al0 = exp2f(mi[mt*2+0] - mn0);
            const float al1 = exp2f(mi[mt*2+1] - mn1);
            float rs0 = 0.f, rs1 = 0.f;
#pragma unroll
            for (int nt = 0; nt < 8; nt++) {
                float p0 = exp2f(s[mt][nt][0] - mn0);
                float p1 = exp2f(s[mt][nt][1] - mn0);
                float p2 = exp2f(s[mt][nt][2] - mn1);
                float p3 = exp2f(s[mt][nt][3] - mn1);
                rs0 += p0 + p1; rs1 += p2 + p3;
                const int ks = nt >> 1, hi = (nt & 1) * 2;
                ph[mt][ks][hi+0] = h2u(__floats2half2_rn(p0, p1));
                ph[mt][ks][hi+1] = h2u(__floats2half2_rn(p2, p3));
            }
#pragma unroll
            for (int off = 1; off <= 2; off <<= 1) {
                rs0 += __shfl_xor_sync(0xffffffffu, rs0, off);
                rs1 += __shfl_xor_sync(0xffffffffu, rs1, off);
            }
            li[mt*2+0] = li[mt*2+0]*al0 + rs0;  mi[mt*2+0] = mn0;
            li[mt*2+1] = li[mt*2+1]*al1 + rs1;  mi[mt*2+1] = mn1;
            const bool skip = __all_sync(0xffffffffu,
                                         (al0 == 1.f) && (al1 == 1.f));
            if (!skip) {
#pragma unroll
                for (int nt = 0; nt < 8; nt++) {
                    o[mt][nt][0] *= al0; o[mt][nt][1] *= al0;
                    o[mt][nt][2] *= al1; o[mt][nt][3] *= al1;
                }
            }
        }

        const unsigned vOff = st * (VS_FL*2);
#pragma unroll
        for (int ks = 0; ks < 4; ks++) {
#pragma unroll
            for (int dv = 0; dv < 4; dv++) {
                unsigned bb[4];
                ldsm4t(bb, vAd[dv] + vOff + ks*(16*VST*2));
                mma16(o[0][2*dv+0], ph[0][ks], &bb[0]);
                mma16(o[0][2*dv+1], ph[0][ks], &bb[2]);
                mma16(o[1][2*dv+0], ph[1][ks], &bb[0]);
                mma16(o[1][2*dv+1], ph[1][ks], &bb[2]);
            }
        }
    }

    const int b = bh >> 4, h = bh & 15;
#pragma unroll
    for (int mt = 0; mt < 2; mt++) {
        const float inv0 = 1.f / li[mt*2+0];
        const float inv1 = 1.f / li[mt*2+1];
        const int r0 = m0 + wid*32 + mt*16 + (lane >> 2);
#pragma unroll
        for (int nt = 0; nt < 8; nt++) {
            const int c = h*64 + nt*8 + (lane & 3)*2;
            *(__half2*)&g_Ah[((size_t)(b*N_ + r0))*D_ + c] =
                __floats2half2_rn(o[mt][nt][0]*inv0, o[mt][nt][1]*inv0);
            *(__half2*)&g_Ah[((size_t)(b*N_ + r0 + 8))*D_ + c] =
                __floats2half2_rn(o[mt][nt][2]*inv1, o[mt][nt][3]*inv1);
        }
    }
}

// ---------------------------------------------------------------------------
extern "C" void kernel_launch(void* const* d_in, const int* in_sizes, int n_in,
                              void* d_out, int out_size)
{
    const float* x    = (const float*)d_in[0];
    const float* rot  = (const float*)d_in[1];
    const float* Wq   = (const float*)d_in[2];
    const float* Wkv  = (const float*)d_in[3];
    const float* Wout = (const float*)d_in[4];
    const float* bout = (const float*)d_in[5];
    float* out = (float*)d_out;

    __half *gXh, *gWqh, *gWkvh, *gWoh, *gAh;
    cudaGetSymbolAddress((void**)&gXh,  g_Xh);
    cudaGetSymbolAddress((void**)&gWqh, g_Wqh);
    cudaGetSymbolAddress((void**)&gWkvh,g_Wkvh);
    cudaGetSymbolAddress((void**)&gWoh, g_Woh);
    cudaGetSymbolAddress((void**)&gAh,  g_Ah);

    cudaFuncSetAttribute(attn_mma,
                         cudaFuncAttributeMaxDynamicSharedMemorySize, ATT_BYTES);
    cudaFuncSetAttribute(gemm_qkv,
                         cudaFuncAttributeMaxDynamicSharedMemorySize, GEMM_BYTES);
    cudaFuncSetAttribute(gemm_out,
                         cudaFuncAttributeMaxDynamicSharedMemorySize, GEMM_BYTES);

    prep_trig<<<(N_*DH_ + 255)/256, 256>>>(rot);
    cvt_h<<<MTOT*D_/4/1024, 256>>>((const float4*)x,    (uint2*)gXh,   MTOT*D_/4);
    cvt_h<<<D_*D_/4/1024,   256>>>((const float4*)Wq,   (uint2*)gWqh,  D_*D_/4);
    cvt_h<<<D_*2*D_/4/1024, 256>>>((const float4*)Wkv,  (uint2*)gWkvh, D_*2*D_/4);
    cvt_h<<<D_*D_/4/1024,   256>>>((const float4*)Wout, (uint2*)gWoh,  D_*D_/4);

    gemm_qkv<<<dim3(24, 64), 256, GEMM_BYTES>>>(gXh, gWqh, gWkvh);
    attn_mma<<<dim3(N_/128, B_*H_), 128, ATT_BYTES>>>();
    gemm_out<<<dim3(8, 64), 256, GEMM_BYTES>>>(gAh, gWoh, out, bout);
}